// round 12
// baseline (speedup 1.0000x reference)
#include <cuda_runtime.h>
#include <cuda_bf16.h>
#include <cuda_fp16.h>
#include <math.h>

#define B_  8
#define L_  2048
#define D_  256
#define H_  128
#define BL_ (B_ * L_)

typedef unsigned int u32;
typedef unsigned long long u64;

// ---------------- device scratch ----------------
__device__ __align__(16) float g_S [(size_t)B_ * L_ * L_];     // [b][q][k]
__device__ __align__(16) __nv_bfloat16 g_pq_hi[(size_t)B_ * L_ * H_];
__device__ __align__(16) __nv_bfloat16 g_pq_lo[(size_t)B_ * L_ * H_];
__device__ __align__(16) __nv_bfloat16 g_pk_hi[(size_t)B_ * L_ * H_];
__device__ __align__(16) __nv_bfloat16 g_pk_lo[(size_t)B_ * L_ * H_];
__device__ __align__(16) __half g_v1t[(size_t)B_ * D_ * L_];   // V^T fp16 [b][d][k]
__device__ __align__(16) __half g_v2t[(size_t)B_ * D_ * L_];   // V^T fp16 [b][d][q]
__device__ u32 g_m1u[BL_];                // row max (branch1), monotone keys
__device__ u32 g_m2u[BL_];                // col max (branch2), monotone keys
__device__ unsigned char g_mask1[BL_];
__device__ unsigned char g_mask2[BL_];
__device__ int g_mask_is_byte;

// ---------------- PTX helpers ----------------
__device__ __forceinline__ u32 smem_u32(const void* p) {
    u32 a;
    asm("{ .reg .u64 t; cvta.to.shared.u64 t, %1; cvt.u32.u64 %0, t; }" : "=r"(a) : "l"(p));
    return a;
}
__device__ __forceinline__ void ldm4(u32* r, u32 addr) {
    asm volatile("ldmatrix.sync.aligned.m8n8.x4.shared.b16 {%0,%1,%2,%3}, [%4];"
        : "=r"(r[0]), "=r"(r[1]), "=r"(r[2]), "=r"(r[3]) : "r"(addr));
}
__device__ __forceinline__ void mma_bf(float* c, const u32* a, const u32* b) {
    asm volatile("mma.sync.aligned.m16n8k16.row.col.f32.bf16.bf16.f32 "
        "{%0,%1,%2,%3}, {%4,%5,%6,%7}, {%8,%9}, {%0,%1,%2,%3};"
        : "+f"(c[0]), "+f"(c[1]), "+f"(c[2]), "+f"(c[3])
        : "r"(a[0]), "r"(a[1]), "r"(a[2]), "r"(a[3]), "r"(b[0]), "r"(b[1]));
}
__device__ __forceinline__ void mma_fp(float* c, const u32* a, const u32* b) {
    asm volatile("mma.sync.aligned.m16n8k16.row.col.f32.f16.f16.f32 "
        "{%0,%1,%2,%3}, {%4,%5,%6,%7}, {%8,%9}, {%0,%1,%2,%3};"
        : "+f"(c[0]), "+f"(c[1]), "+f"(c[2]), "+f"(c[3])
        : "r"(a[0]), "r"(a[1]), "r"(a[2]), "r"(a[3]), "r"(b[0]), "r"(b[1]));
}
#define CPA16(sm, gp)  asm volatile("cp.async.ca.shared.global [%0], [%1], 16;" :: "r"(sm), "l"(gp))
#define CPA_COMMIT()   asm volatile("cp.async.commit_group;" ::: "memory")
template<int N> __device__ __forceinline__ void cpa_wait() {
    asm volatile("cp.async.wait_group %0;" :: "n"(N) : "memory");
}

__device__ __forceinline__ void split_bf(float v, __nv_bfloat16& h, __nv_bfloat16& l) {
    h = __float2bfloat16_rn(v);
    l = __float2bfloat16_rn(v - __bfloat162float(h));
}
__device__ __forceinline__ u64 pack4(__nv_bfloat16 a, __nv_bfloat16 b,
                                     __nv_bfloat16 c, __nv_bfloat16 d) {
    union { __nv_bfloat16 h[4]; u64 u; } x;
    x.h[0] = a; x.h[1] = b; x.h[2] = c; x.h[3] = d;
    return x.u;
}
__device__ __forceinline__ u64 pack4h(__half a, __half b, __half c, __half d) {
    union { __half h[4]; u64 u; } x;
    x.h[0] = a; x.h[1] = b; x.h[2] = c; x.h[3] = d;
    return x.u;
}
__device__ __forceinline__ u32 pack2(__nv_bfloat16 a, __nv_bfloat16 b) {
    union { __nv_bfloat16 h[2]; u32 u; } x;
    x.h[0] = a; x.h[1] = b;
    return x.u;
}
__device__ __forceinline__ u32 pack2h(__half a, __half b) {
    union { __half h[2]; u32 u; } x;
    x.h[0] = a; x.h[1] = b;
    return x.u;
}
// monotone float<->uint for atomicMax
__device__ __forceinline__ u32 menc(float f) {
    u32 b = __float_as_uint(f);
    return (b & 0x80000000u) ? ~b : (b | 0x80000000u);
}
__device__ __forceinline__ float mdec(u32 k) {
    u32 b = (k & 0x80000000u) ? (k ^ 0x80000000u) : ~k;
    return __uint_as_float(b);
}

// tile geometry: rows x 32 halves, padded row stride 80B
#define TB    10240                  // 128 rows x 80B
#define STG4  (4 * TB)               // scores/proj stage: Ah|Al|Bh|Bl
#define TOFF  1024
#define SSMEM (TOFF + 4 * STG4)      // scores 4-stage
#define PSMEM (TOFF + 2 * STG4)      // proj double buffer

// branch stage: S fp32 staging | W fp16 panel | V fp16 panels
#define BSTG_W 18432                 // S staging region size (br1: 128*144B; br2: 32*528B)
#define BSTG_V (BSTG_W + TB)         // 28672
#define BSTG   (BSTG_V + 2 * TB)     // 49152
#define BTOFF  8192
#define BSMEM  (BTOFF + 4 * BSTG)    // 204800

// bf16x3 chunk (proj/scores): 8 warps, warp tile 32x64 over 128x128
__device__ __forceinline__ void gemm_chunk(u32 sb, int stage, float (&acc)[2][8][4],
                                           int lane, int m0w, int n0w)
{
    const u32 tbase = sb + TOFF + stage * STG4;
    #pragma unroll
    for (int ks = 0; ks < 2; ks++) {
        u32 ah[2][4], al[2][4];
        #pragma unroll
        for (int mi = 0; mi < 2; mi++) {
            u32 a = tbase + (u32)(m0w + mi * 16 + (lane & 15)) * 80 + ks * 32 + (lane >> 4) * 16;
            ldm4(ah[mi], a);
            ldm4(al[mi], a + TB);
        }
        u32 bh[8][2], bl[8][2];
        #pragma unroll
        for (int np = 0; np < 4; np++) {
            int g = lane >> 3, lr = lane & 7;
            u32 a = tbase + 2 * TB
                  + (u32)(n0w + np * 16 + (g >> 1) * 8 + lr) * 80 + ks * 32 + (g & 1) * 16;
            u32 r4[4];
            ldm4(r4, a);
            bh[2 * np][0] = r4[0]; bh[2 * np][1] = r4[1];
            bh[2 * np + 1][0] = r4[2]; bh[2 * np + 1][1] = r4[3];
            ldm4(r4, a + TB);
            bl[2 * np][0] = r4[0]; bl[2 * np][1] = r4[1];
            bl[2 * np + 1][0] = r4[2]; bl[2 * np + 1][1] = r4[3];
        }
        #pragma unroll
        for (int mi = 0; mi < 2; mi++)
            #pragma unroll
            for (int ni = 0; ni < 8; ni++) {
                mma_bf(acc[mi][ni], ah[mi], bh[ni]);
                mma_bf(acc[mi][ni], ah[mi], bl[ni]);
                mma_bf(acc[mi][ni], al[mi], bh[ni]);
            }
    }
}

// fp16 single-MMA chunk (branch): A = W panel, B = V panels
__device__ __forceinline__ void gemm_chunk_f16(u32 sb, int stage, float (&acc)[2][8][4],
                                               int lane, int m0w, int n0w)
{
    const u32 tbase = sb + BTOFF + stage * BSTG;
    #pragma unroll
    for (int ks = 0; ks < 2; ks++) {
        u32 aw[2][4];
        #pragma unroll
        for (int mi = 0; mi < 2; mi++) {
            u32 a = tbase + BSTG_W
                  + (u32)(m0w + mi * 16 + (lane & 15)) * 80 + ks * 32 + (lane >> 4) * 16;
            ldm4(aw[mi], a);
        }
        u32 bh[8][2];
        #pragma unroll
        for (int np = 0; np < 4; np++) {
            int g = lane >> 3, lr = lane & 7;
            u32 a = tbase + BSTG_V
                  + (u32)(n0w + np * 16 + (g >> 1) * 8 + lr) * 80 + ks * 32 + (g & 1) * 16;
            u32 r4[4];
            ldm4(r4, a);
            bh[2 * np][0] = r4[0]; bh[2 * np][1] = r4[1];
            bh[2 * np + 1][0] = r4[2]; bh[2 * np + 1][1] = r4[3];
        }
        #pragma unroll
        for (int mi = 0; mi < 2; mi++)
            #pragma unroll
            for (int ni = 0; ni < 8; ni++)
                mma_fp(acc[mi][ni], aw[mi], bh[ni]);
    }
}

// ---------------- masks (+ atomic key init) ----------------
__global__ void detect_mask_kernel(const unsigned char* m) {
    __shared__ int flag;
    if (threadIdx.x == 0) flag = 0;
    __syncthreads();
    for (int i = threadIdx.x; i < BL_; i += blockDim.x)
        if ((i & 3) && m[i]) flag = 1;
    __syncthreads();
    if (threadIdx.x == 0) g_mask_is_byte = flag;
}
__global__ void build_mask_kernel(const void* m1, const void* m2) {
    int i = blockIdx.x * blockDim.x + threadIdx.x;
    if (i >= BL_) return;
    g_m1u[i] = 0u;
    g_m2u[i] = 0u;
    if (g_mask_is_byte) {
        g_mask1[i] = ((const unsigned char*)m1)[i] ? 1 : 0;
        g_mask2[i] = ((const unsigned char*)m2)[i] ? 1 : 0;
    } else {
        g_mask1[i] = ((const int*)m1)[i] ? 1 : 0;
        g_mask2[i] = ((const int*)m2)[i] ? 1 : 0;
    }
}

// ---------------- V transpose + fp16 convert ----------------
__global__ void __launch_bounds__(256) vsplit_kernel(
    const float* __restrict__ V1, const float* __restrict__ V2)
{
    __shared__ float ts[64][65];
    const int which = blockIdx.z & 1, b = blockIdx.z >> 1;
    const float* V = (which ? V2 : V1) + (size_t)b * L_ * D_;
    __half* dh = (which ? g_v2t : g_v1t) + (size_t)b * D_ * L_;
    const int i0 = blockIdx.x * 64, d0 = blockIdx.y * 64;
    const int tid = threadIdx.x;
    {
        const int r = tid >> 2, c0 = (tid & 3) * 16;
        #pragma unroll
        for (int j = 0; j < 4; j++) {
            float4 v = *(const float4*)&V[(size_t)(i0 + r) * D_ + d0 + c0 + 4 * j];
            ts[r][c0 + 4 * j] = v.x; ts[r][c0 + 4 * j + 1] = v.y;
            ts[r][c0 + 4 * j + 2] = v.z; ts[r][c0 + 4 * j + 3] = v.w;
        }
    }
    __syncthreads();
    {
        const int rd = tid >> 2, cw = (tid & 3) * 16;
        #pragma unroll
        for (int j = 0; j < 4; j++) {
            __half h[4];
            #pragma unroll
            for (int e = 0; e < 4; e++) h[e] = __float2half_rn(ts[cw + 4 * j + e][rd]);
            size_t o = (size_t)(d0 + rd) * L_ + i0 + cw + 4 * j;
            *(u64*)&dh[o] = pack4h(h[0], h[1], h[2], h[3]);
        }
    }
}

// ---------------- proj: relu(X W^T)(*scaling) -> bf16 hi/lo ----------------
__global__ void __launch_bounds__(256, 1) proj_kernel(
    const float* __restrict__ Q, const float* __restrict__ K,
    const float* __restrict__ Wq, const float* __restrict__ Wk,
    const float* __restrict__ scaling)
{
    extern __shared__ __align__(16) char smem[];
    const u32 sb = smem_u32(smem);
    const int tid = threadIdx.x, lane = tid & 31, w = tid >> 5;
    const int m0w = (w & 3) * 32, n0w = (w >> 2) * 64;
    const int which = blockIdx.y, row0 = blockIdx.x * 128;
    const float* X  = which ? K : Q;
    const float* Wm = which ? Wk : Wq;
    __nv_bfloat16* oh = which ? g_pk_hi : g_pq_hi;
    __nv_bfloat16* ol = which ? g_pk_lo : g_pq_lo;

    float acc[2][8][4];
    #pragma unroll
    for (int mi = 0; mi < 2; mi++)
        #pragma unroll
        for (int ni = 0; ni < 8; ni++)
            #pragma unroll
            for (int e = 0; e < 4; e++) acc[mi][ni][e] = 0.f;

    const int r_ = tid >> 1, hf = tid & 1;
    float4 xa[4], wb[4];

    auto ldchunk = [&](int c) {
        const int k0 = c * 32;
        const float* xr = X  + (size_t)(row0 + r_) * D_ + k0 + hf * 16;
        const float* wr = Wm + (size_t)r_ * D_ + k0 + hf * 16;
        #pragma unroll
        for (int j = 0; j < 4; j++) { xa[j] = *(const float4*)&xr[4 * j];
                                      wb[j] = *(const float4*)&wr[4 * j]; }
    };
    auto stchunk = [&](int buf) {
        char* tp = smem + TOFF + buf * STG4;
        const u32 off = (u32)r_ * 80 + hf * 32;
        #pragma unroll
        for (int j = 0; j < 4; j++) {
            __nv_bfloat16 h[4], l[4];
            split_bf(xa[j].x, h[0], l[0]); split_bf(xa[j].y, h[1], l[1]);
            split_bf(xa[j].z, h[2], l[2]); split_bf(xa[j].w, h[3], l[3]);
            *(u64*)(tp + off + j * 8)      = pack4(h[0], h[1], h[2], h[3]);
            *(u64*)(tp + TB + off + j * 8) = pack4(l[0], l[1], l[2], l[3]);
            split_bf(wb[j].x, h[0], l[0]); split_bf(wb[j].y, h[1], l[1]);
            split_bf(wb[j].z, h[2], l[2]); split_bf(wb[j].w, h[3], l[3]);
            *(u64*)(tp + 2 * TB + off + j * 8) = pack4(h[0], h[1], h[2], h[3]);
            *(u64*)(tp + 3 * TB + off + j * 8) = pack4(l[0], l[1], l[2], l[3]);
        }
    };

    ldchunk(0);
    stchunk(0);
    __syncthreads();
    for (int c = 0; c < 8; c++) {
        if (c + 1 < 8) ldchunk(c + 1);
        gemm_chunk(sb, c & 1, acc, lane, m0w, n0w);
        if (c + 1 < 8) stchunk((c + 1) & 1);
        __syncthreads();
    }

    #pragma unroll
    for (int mi = 0; mi < 2; mi++) {
        const int rr = row0 + m0w + mi * 16 + (lane >> 2);
        #pragma unroll
        for (int ni = 0; ni < 8; ni++) {
            const int cc = n0w + ni * 8 + 2 * (lane & 3);
            float s0 = 1.f, s1 = 1.f;
            if (which) { s0 = __ldg(&scaling[cc]); s1 = __ldg(&scaling[cc + 1]); }
            float v00 = fmaxf(acc[mi][ni][0], 0.f) * s0;
            float v01 = fmaxf(acc[mi][ni][1], 0.f) * s1;
            float v10 = fmaxf(acc[mi][ni][2], 0.f) * s0;
            float v11 = fmaxf(acc[mi][ni][3], 0.f) * s1;
            __nv_bfloat16 h0, l0, h1, l1;
            split_bf(v00, h0, l0); split_bf(v01, h1, l1);
            *(u32*)&oh[(size_t)rr * H_ + cc] = pack2(h0, h1);
            *(u32*)&ol[(size_t)rr * H_ + cc] = pack2(l0, l1);
            split_bf(v10, h0, l0); split_bf(v11, h1, l1);
            *(u32*)&oh[(size_t)(rr + 8) * H_ + cc] = pack2(h0, h1);
            *(u32*)&ol[(size_t)(rr + 8) * H_ + cc] = pack2(l0, l1);
        }
    }
}

// ---------------- scores: S = pq pk^T; stores S + row/col masked maxima ----------------
__global__ void __launch_bounds__(256, 1) scores_kernel()
{
    extern __shared__ __align__(16) char smem[];
    const u32 sb = smem_u32(smem);
    const int tid = threadIdx.x, lane = tid & 31, w = tid >> 5;
    const int m0w = (w & 3) * 32, n0w = (w >> 2) * 64;
    const int b = blockIdx.z, row0 = blockIdx.y * 128, col0 = blockIdx.x * 128;
    const __nv_bfloat16* aqh = g_pq_hi + (size_t)(b * L_ + row0) * H_;
    const __nv_bfloat16* aql = g_pq_lo + (size_t)(b * L_ + row0) * H_;
    const __nv_bfloat16* bkh = g_pk_hi + (size_t)(b * L_ + col0) * H_;
    const __nv_bfloat16* bkl = g_pk_lo + (size_t)(b * L_ + col0) * H_;
    float* S = g_S + (size_t)b * L_ * L_;

    float acc[2][8][4];
    #pragma unroll
    for (int mi = 0; mi < 2; mi++)
        #pragma unroll
        for (int ni = 0; ni < 8; ni++)
            #pragma unroll
            for (int e = 0; e < 4; e++) acc[mi][ni][e] = 0.f;

    auto cpAB = [&](int c, int stage) {
        const int k0 = c * 32;
        const u32 base = sb + TOFF + stage * STG4;
        #pragma unroll
        for (int t = 0; t < 2; t++) {
            int idx = tid + t * 256;
            int rr = idx >> 2, seg = idx & 3;
            u32 so = base + (u32)rr * 80 + seg * 16;
            size_t go = (size_t)rr * H_ + k0 + seg * 8;
            CPA16(so,          aqh + go);
            CPA16(so + TB,     aql + go);
            CPA16(so + 2 * TB, bkh + go);
            CPA16(so + 3 * TB, bkl + go);
        }
        CPA_COMMIT();
    };

    cpAB(0, 0); cpAB(1, 1); cpAB(2, 2); cpAB(3, 3);
    #pragma unroll
    for (int c = 0; c < 4; c++) {
        if      (c == 0) cpa_wait<3>();
        else if (c == 1) cpa_wait<2>();
        else if (c == 2) cpa_wait<1>();
        else             cpa_wait<0>();
        __syncthreads();
        gemm_chunk(sb, c, acc, lane, m0w, n0w);
    }

    // direct S stores
    #pragma unroll
    for (int mi = 0; mi < 2; mi++) {
        const int rr = m0w + mi * 16 + (lane >> 2);
        float* p0 = S + (size_t)(row0 + rr) * L_ + col0 + n0w + 2 * (lane & 3);
        #pragma unroll
        for (int ni = 0; ni < 8; ni++) {
            *(float2*)(p0 + ni * 8)          = make_float2(acc[mi][ni][0], acc[mi][ni][1]);
            *(float2*)(p0 + 8 * L_ + ni * 8) = make_float2(acc[mi][ni][2], acc[mi][ni][3]);
        }
    }

    // masked column max (mask over q rows) -> g_m2u
    {
        const unsigned char* mk2 = g_mask2 + (b << 11);
        float cmax[8][2];
        #pragma unroll
        for (int ni = 0; ni < 8; ni++) { cmax[ni][0] = -INFINITY; cmax[ni][1] = -INFINITY; }
        #pragma unroll
        for (int mi = 0; mi < 2; mi++) {
            const int rr = row0 + m0w + mi * 16 + (lane >> 2);
            const bool u0 = mk2[rr] == 0;
            const bool u1 = mk2[rr + 8] == 0;
            #pragma unroll
            for (int ni = 0; ni < 8; ni++) {
                if (u0) {
                    cmax[ni][0] = fmaxf(cmax[ni][0], acc[mi][ni][0]);
                    cmax[ni][1] = fmaxf(cmax[ni][1], acc[mi][ni][1]);
                }
                if (u1) {
                    cmax[ni][0] = fmaxf(cmax[ni][0], acc[mi][ni][2]);
                    cmax[ni][1] = fmaxf(cmax[ni][1], acc[mi][ni][3]);
                }
            }
        }
        #pragma unroll
        for (int off = 4; off <= 16; off <<= 1)
            #pragma unroll
            for (int ni = 0; ni < 8; ni++) {
                cmax[ni][0] = fmaxf(cmax[ni][0], __shfl_xor_sync(0xffffffffu, cmax[ni][0], off));
                cmax[ni][1] = fmaxf(cmax[ni][1], __shfl_xor_sync(0xffffffffu, cmax[ni][1], off));
            }
        if ((lane >> 2) == 0) {
            u32* mu = g_m2u + (b << 11) + col0 + n0w + 2 * (lane & 3);
            #pragma unroll
            for (int ni = 0; ni < 8; ni++) {
                atomicMax(&mu[ni * 8],     menc(cmax[ni][0]));
                atomicMax(&mu[ni * 8 + 1], menc(cmax[ni][1]));
            }
        }
    }

    // masked row max (mask over k cols) -> g_m1u
    {
        const unsigned char* mk1 = g_mask1 + (b << 11);
        const int cb = col0 + n0w + 2 * (lane & 3);
        float rmax[4] = { -INFINITY, -INFINITY, -INFINITY, -INFINITY };
        #pragma unroll
        for (int ni = 0; ni < 8; ni++) {
            const bool u0 = mk1[cb + ni * 8] == 0;
            const bool u1 = mk1[cb + ni * 8 + 1] == 0;
            #pragma unroll
            for (int mi = 0; mi < 2; mi++) {
                float v0 = u0 ? acc[mi][ni][0] : -INFINITY;
                float v1 = u1 ? acc[mi][ni][1] : -INFINITY;
                rmax[2 * mi] = fmaxf(rmax[2 * mi], fmaxf(v0, v1));
                float v2 = u0 ? acc[mi][ni][2] : -INFINITY;
                float v3 = u1 ? acc[mi][ni][3] : -INFINITY;
                rmax[2 * mi + 1] = fmaxf(rmax[2 * mi + 1], fmaxf(v2, v3));
            }
        }
        #pragma unroll
        for (int off = 1; off <= 2; off <<= 1)
            #pragma unroll
            for (int i = 0; i < 4; i++)
                rmax[i] = fmaxf(rmax[i], __shfl_xor_sync(0xffffffffu, rmax[i], off));
        if ((lane & 3) == 0) {
            u32* mu = g_m1u + (b << 11) + row0 + m0w + (lane >> 2);
            atomicMax(&mu[0],  menc(rmax[0]));
            atomicMax(&mu[8],  menc(rmax[1]));
            atomicMax(&mu[16], menc(rmax[2]));
            atomicMax(&mu[24], menc(rmax[3]));
        }
    }
}

// ---------------- branch: fused exp + fp16 GEMM, 128x256 tile, 512 thr ----------------
// br0: out1[q,d] = (1/l1[q]) sum_k !m1[k] exp(S[q,k]-m1[q]) V1[k,d]
// br1: out2[k,d] = (1/l2[k]) sum_q !m2[q] exp(S[q,k]-m2[k]) V2[q,d]
__global__ void __launch_bounds__(512, 1) branch_kernel(float* __restrict__ out)
{
    extern __shared__ __align__(16) char smem[];
    const u32 sb = smem_u32(smem);
    const int tid = threadIdx.x, lane = tid & 31, w = tid >> 5;
    const int m0w = (w & 3) * 32, n0w = (w >> 2) * 64;   // 16 warps: 4x4
    const int row0 = blockIdx.x * 128;
    const int br = blockIdx.z & 1, b = blockIdx.z >> 1;

    const float* Sb = g_S + (size_t)b * L_ * L_;
    const unsigned char* mk = (br ? g_mask2 : g_mask1) + (b << 11);      // inner mask
    const u32* mu = (br ? g_m2u : g_m1u) + (b << 11) + row0;             // row maxes
    const __half* vt = (br ? g_v2t : g_v1t) + (size_t)b * D_ * L_;
    float* ob = out + (br ? (size_t)B_ * L_ * D_ : 0) + (size_t)(b * L_ + row0) * D_;

    float* s_m = (float*)(smem);                 // [128] row max, then 1/l
    unsigned char* mask_s = (unsigned char*)(smem + 1024);   // [2048]
    float* lbuf = (float*)(smem + 3072);         // [512]
    if (tid < 128) s_m[tid] = mdec(mu[tid]);
    ((u32*)mask_s)[tid] = ((const u32*)mk)[tid];
    __syncthreads();

    float acc[2][8][4];
    #pragma unroll
    for (int mi = 0; mi < 2; mi++)
        #pragma unroll
        for (int ni = 0; ni < 8; ni++)
            #pragma unroll
            for (int e = 0; e < 4; e++) acc[mi][ni][e] = 0.f;
    float lreg = 0.f;

    const int part = w >> 2;              // inner segment 0..3
    const int arow = m0w + lane;          // A-operand row owned for convert
    const float mrow = s_m[arow];

    auto cpc = [&](int c, int stage) {
        const int i0 = c * 32;
        const u32 base = sb + BTOFF + stage * BSTG;
        if (!br) {
            #pragma unroll
            for (int t = 0; t < 2; t++) {   // S: 128 rows x 32 floats, dest stride 144B
                int idx = tid + t * 512;
                int r = idx >> 3, seg = idx & 7;
                CPA16(base + (u32)r * 144 + seg * 16,
                      Sb + (size_t)(row0 + r) * L_ + i0 + seg * 4);
            }
        } else {
            #pragma unroll
            for (int t = 0; t < 2; t++) {   // S^T source: 32 q-rows x 128 k, dest stride 528B
                int idx = tid + t * 512;
                int r = idx >> 5, seg = idx & 31;
                CPA16(base + (u32)r * 528 + seg * 16,
                      Sb + (size_t)(i0 + r) * L_ + row0 + seg * 4);
            }
        }
        #pragma unroll
        for (int t = 0; t < 2; t++) {       // V: 256 rows x 32 halves
            int idx = tid + t * 512;
            int rr = idx >> 2, seg = idx & 3;
            CPA16(base + BSTG_V + (u32)rr * 80 + seg * 16,
                  vt + (size_t)rr * L_ + i0 + seg * 8);
        }
    };

    auto convert = [&](int c, int stage) {
        const int i0 = c * 32;
        char* bp = smem + BTOFF + stage * BSTG;
        float sv[8];
        if (!br) {
            const float* sp = (const float*)bp + (u32)arow * 36 + part * 8;
            float4 a = *(const float4*)sp;
            float4 bq = *(const float4*)(sp + 4);
            sv[0] = a.x; sv[1] = a.y; sv[2] = a.z; sv[3] = a.w;
            sv[4] = bq.x; sv[5] = bq.y; sv[6] = bq.z; sv[7] = bq.w;
        } else {
            #pragma unroll
            for (int j = 0; j < 8; j++)
                sv[j] = *((const float*)bp + (u32)(part * 8 + j) * 132 + arow);
        }
        u32 pk[4];
        #pragma unroll
        for (int j = 0; j < 4; j++) {
            float e0 = mask_s[i0 + part * 8 + 2 * j]     ? 0.f : __expf(sv[2 * j] - mrow);
            float e1 = mask_s[i0 + part * 8 + 2 * j + 1] ? 0.f : __expf(sv[2 * j + 1] - mrow);
            lreg += e0 + e1;
            pk[j] = pack2h(__float2half_rn(e0), __float2half_rn(e1));
        }
        *(uint4*)(bp + BSTG_W + (u32)arow * 80 + part * 16) = make_uint4(pk[0], pk[1], pk[2], pk[3]);
    };

    cpc(0, 0); CPA_COMMIT();
    cpc(1, 1); CPA_COMMIT();
    cpc(2, 2); CPA_COMMIT();
    cpc(3, 3); CPA_COMMIT();

    for (int c = 0; c < 64; c++) {
        cpa_wait<3>();
        __syncthreads();
        convert(c, c & 3);
        __syncthreads();          // W panel is cross-warp: all 4 parts must land before MMA
        gemm_chunk_f16(sb, c & 3, acc, lane, m0w, n0w);
        __syncthreads();
        if (c + 4 < 64) cpc(c + 4, (c + 4) & 3);
        CPA_COMMIT();
    }

    // reduce l and invert
    lbuf[arow * 4 + part] = lreg;
    __syncthreads();
    if (tid < 128)
        s_m[tid] = 1.f / (lbuf[tid * 4] + lbuf[tid * 4 + 1] + lbuf[tid * 4 + 2] + lbuf[tid * 4 + 3]);
    __syncthreads();

    #pragma unroll
    for (int mi = 0; mi < 2; mi++) {
        const int rr = m0w + mi * 16 + (lane >> 2);
        const float sc0 = s_m[rr], sc1 = s_m[rr + 8];
        float* p0 = ob + (size_t)rr * D_ + n0w + 2 * (lane & 3);
        float* p1 = p0 + 8 * D_;
        #pragma unroll
        for (int ni = 0; ni < 8; ni++) {
            *(float2*)(p0 + ni * 8) = make_float2(acc[mi][ni][0] * sc0, acc[mi][ni][1] * sc0);
            *(float2*)(p1 + ni * 8) = make_float2(acc[mi][ni][2] * sc1, acc[mi][ni][3] * sc1);
        }
    }
}

// ---------------------------------------------------------------------------
extern "C" void kernel_launch(void* const* d_in, const int* in_sizes, int n_in,
                              void* d_out, int out_size)
{
    const float* queries = (const float*)d_in[0];
    const float* keys    = (const float*)d_in[1];
    const float* values1 = (const float*)d_in[2];
    const void*  mask1   = d_in[3];
    const float* values2 = (const float*)d_in[4];
    const void*  mask2   = d_in[5];
    const float* Wq      = (const float*)d_in[6];
    const float* Wk      = (const float*)d_in[7];
    const float* scaling = (const float*)d_in[8];
    float* out = (float*)d_out;

    cudaFuncSetAttribute(proj_kernel,   cudaFuncAttributeMaxDynamicSharedMemorySize, PSMEM);
    cudaFuncSetAttribute(scores_kernel, cudaFuncAttributeMaxDynamicSharedMemorySize, SSMEM);
    cudaFuncSetAttribute(branch_kernel, cudaFuncAttributeMaxDynamicSharedMemorySize, BSMEM);

    detect_mask_kernel<<<1, 256>>>((const unsigned char*)mask1);
    build_mask_kernel<<<(BL_ + 255) / 256, 256>>>(mask1, mask2);

    vsplit_kernel<<<dim3(L_ / 64, D_ / 64, B_ * 2), 256>>>(values1, values2);

    proj_kernel<<<dim3((B_ * L_) / 128, 2), 256, PSMEM>>>(queries, keys, Wq, Wk, scaling);

    scores_kernel<<<dim3(L_ / 128, L_ / 128, B_), 256, SSMEM>>>();

    branch_kernel<<<dim3(L_ / 128, 1, B_ * 2), 512, BSMEM>>>(out);
}

// round 13
// speedup vs baseline: 1.1083x; 1.1083x over previous
#include <cuda_runtime.h>
#include <cuda_bf16.h>
#include <cuda_fp16.h>
#include <math.h>

#define B_  8
#define L_  2048
#define D_  256
#define H_  128
#define BL_ (B_ * L_)

typedef unsigned int u32;
typedef unsigned long long u64;

// ---------------- device scratch ----------------
__device__ __align__(16) float g_S [(size_t)B_ * L_ * L_];     // [b][q][k]
__device__ __align__(16) __half g_w1[(size_t)B_ * L_ * L_];    // weights br1 [b][q][k]
__device__ __align__(16) __half g_w2[(size_t)B_ * L_ * L_];    // weights br2 [b][k][q]
__device__ __align__(16) __nv_bfloat16 g_pq_hi[(size_t)B_ * L_ * H_];
__device__ __align__(16) __nv_bfloat16 g_pq_lo[(size_t)B_ * L_ * H_];
__device__ __align__(16) __nv_bfloat16 g_pk_hi[(size_t)B_ * L_ * H_];
__device__ __align__(16) __nv_bfloat16 g_pk_lo[(size_t)B_ * L_ * H_];
__device__ __align__(16) __half g_v1t[(size_t)B_ * D_ * L_];   // V^T fp16 [b][d][k]
__device__ __align__(16) __half g_v2t[(size_t)B_ * D_ * L_];   // V^T fp16 [b][d][q]
__device__ u32 g_m1u[BL_];                // row max (branch1), monotone keys
__device__ u32 g_m2u[BL_];                // col max (branch2), monotone keys
__device__ float g_l1p[32 * BL_];         // per-k-strip partial row sums
__device__ float g_l2p[4 * BL_];          // per-q-part partial col sums
__device__ unsigned char g_mask1[BL_];
__device__ unsigned char g_mask2[BL_];
__device__ int g_mask_is_byte;

// ---------------- PTX helpers ----------------
__device__ __forceinline__ u32 smem_u32(const void* p) {
    u32 a;
    asm("{ .reg .u64 t; cvta.to.shared.u64 t, %1; cvt.u32.u64 %0, t; }" : "=r"(a) : "l"(p));
    return a;
}
__device__ __forceinline__ void ldm4(u32* r, u32 addr) {
    asm volatile("ldmatrix.sync.aligned.m8n8.x4.shared.b16 {%0,%1,%2,%3}, [%4];"
        : "=r"(r[0]), "=r"(r[1]), "=r"(r[2]), "=r"(r[3]) : "r"(addr));
}
__device__ __forceinline__ void mma_bf(float* c, const u32* a, const u32* b) {
    asm volatile("mma.sync.aligned.m16n8k16.row.col.f32.bf16.bf16.f32 "
        "{%0,%1,%2,%3}, {%4,%5,%6,%7}, {%8,%9}, {%0,%1,%2,%3};"
        : "+f"(c[0]), "+f"(c[1]), "+f"(c[2]), "+f"(c[3])
        : "r"(a[0]), "r"(a[1]), "r"(a[2]), "r"(a[3]), "r"(b[0]), "r"(b[1]));
}
__device__ __forceinline__ void mma_fp(float* c, const u32* a, const u32* b) {
    asm volatile("mma.sync.aligned.m16n8k16.row.col.f32.f16.f16.f32 "
        "{%0,%1,%2,%3}, {%4,%5,%6,%7}, {%8,%9}, {%0,%1,%2,%3};"
        : "+f"(c[0]), "+f"(c[1]), "+f"(c[2]), "+f"(c[3])
        : "r"(a[0]), "r"(a[1]), "r"(a[2]), "r"(a[3]), "r"(b[0]), "r"(b[1]));
}
#define CPA16(sm, gp)  asm volatile("cp.async.ca.shared.global [%0], [%1], 16;" :: "r"(sm), "l"(gp))
#define CPA_COMMIT()   asm volatile("cp.async.commit_group;" ::: "memory")
template<int N> __device__ __forceinline__ void cpa_wait() {
    asm volatile("cp.async.wait_group %0;" :: "n"(N) : "memory");
}

__device__ __forceinline__ void split_bf(float v, __nv_bfloat16& h, __nv_bfloat16& l) {
    h = __float2bfloat16_rn(v);
    l = __float2bfloat16_rn(v - __bfloat162float(h));
}
__device__ __forceinline__ u64 pack4(__nv_bfloat16 a, __nv_bfloat16 b,
                                     __nv_bfloat16 c, __nv_bfloat16 d) {
    union { __nv_bfloat16 h[4]; u64 u; } x;
    x.h[0] = a; x.h[1] = b; x.h[2] = c; x.h[3] = d;
    return x.u;
}
__device__ __forceinline__ u64 pack4h(__half a, __half b, __half c, __half d) {
    union { __half h[4]; u64 u; } x;
    x.h[0] = a; x.h[1] = b; x.h[2] = c; x.h[3] = d;
    return x.u;
}
__device__ __forceinline__ u32 pack2(__nv_bfloat16 a, __nv_bfloat16 b) {
    union { __nv_bfloat16 h[2]; u32 u; } x;
    x.h[0] = a; x.h[1] = b;
    return x.u;
}
__device__ __forceinline__ u32 pack2h(__half a, __half b) {
    union { __half h[2]; u32 u; } x;
    x.h[0] = a; x.h[1] = b;
    return x.u;
}
// monotone float<->uint for atomicMax
__device__ __forceinline__ u32 menc(float f) {
    u32 b = __float_as_uint(f);
    return (b & 0x80000000u) ? ~b : (b | 0x80000000u);
}
__device__ __forceinline__ float mdec(u32 k) {
    u32 b = (k & 0x80000000u) ? (k ^ 0x80000000u) : ~k;
    return __uint_as_float(b);
}

// tile geometry: rows x 32 halves, padded row stride 80B
#define TB    10240                  // 128 rows x 80B
#define STG4  (4 * TB)               // scores/proj stage: Ah|Al|Bh|Bl
#define TOFF  1024
#define SSMEM (TOFF + 4 * STG4)      // scores 4-stage
#define PSMEM (TOFF + 2 * STG4)      // proj double buffer
#define BSTG  (3 * TB)               // branch stage: A(128) | B(256)
#define BSMEM (TOFF + 4 * BSTG)      // 123904

// weights kernel smem layout (dynamic)
#define W_SROW   68                  // S chunk row stride (floats), 272B (16B mult)
#define W_SBUF   (64 * W_SROW * 4)   // 17408 per buffer
#define W_TILE   (2 * W_SBUF)        // float tile[64][69] at 34816
#define W_TROW   69
#define W_LSM    (W_TILE + 64 * W_TROW * 4)   // 52480: float lsm[256]
#define W_M1S    (W_LSM + 1024)               // 53504: float m1s[512]
#define W_M2S    (W_M1S + 2048)               // 55552: float m2s[64]
#define W_MK2    (W_M2S + 256)                // 55808: uchar mask2s[512]
#define W_MK1    (W_MK2 + 512)                // 56320: uchar mask1s[64]
#define WSMEM    (W_MK1 + 64)                 // 56384

// bf16x3 chunk (proj/scores): 8 warps, warp tile 32x64 over 128x128
__device__ __forceinline__ void gemm_chunk(u32 sb, int stage, float (&acc)[2][8][4],
                                           int lane, int m0w, int n0w)
{
    const u32 tbase = sb + TOFF + stage * STG4;
    #pragma unroll
    for (int ks = 0; ks < 2; ks++) {
        u32 ah[2][4], al[2][4];
        #pragma unroll
        for (int mi = 0; mi < 2; mi++) {
            u32 a = tbase + (u32)(m0w + mi * 16 + (lane & 15)) * 80 + ks * 32 + (lane >> 4) * 16;
            ldm4(ah[mi], a);
            ldm4(al[mi], a + TB);
        }
        u32 bh[8][2], bl[8][2];
        #pragma unroll
        for (int np = 0; np < 4; np++) {
            int g = lane >> 3, lr = lane & 7;
            u32 a = tbase + 2 * TB
                  + (u32)(n0w + np * 16 + (g >> 1) * 8 + lr) * 80 + ks * 32 + (g & 1) * 16;
            u32 r4[4];
            ldm4(r4, a);
            bh[2 * np][0] = r4[0]; bh[2 * np][1] = r4[1];
            bh[2 * np + 1][0] = r4[2]; bh[2 * np + 1][1] = r4[3];
            ldm4(r4, a + TB);
            bl[2 * np][0] = r4[0]; bl[2 * np][1] = r4[1];
            bl[2 * np + 1][0] = r4[2]; bl[2 * np + 1][1] = r4[3];
        }
        #pragma unroll
        for (int mi = 0; mi < 2; mi++)
            #pragma unroll
            for (int ni = 0; ni < 8; ni++) {
                mma_bf(acc[mi][ni], ah[mi], bh[ni]);
                mma_bf(acc[mi][ni], ah[mi], bl[ni]);
                mma_bf(acc[mi][ni], al[mi], bh[ni]);
            }
    }
}

// fp16 single-MMA chunk (branch): 16 warps, warp tile 32x64 over 128x256
__device__ __forceinline__ void gemm_chunk_f16(u32 sb, int stage, float (&acc)[2][8][4],
                                               int lane, int m0w, int n0w)
{
    const u32 tbase = sb + TOFF + stage * BSTG;
    #pragma unroll
    for (int ks = 0; ks < 2; ks++) {
        u32 aw[2][4];
        #pragma unroll
        for (int mi = 0; mi < 2; mi++) {
            u32 a = tbase + (u32)(m0w + mi * 16 + (lane & 15)) * 80 + ks * 32 + (lane >> 4) * 16;
            ldm4(aw[mi], a);
        }
        u32 bh[8][2];
        #pragma unroll
        for (int np = 0; np < 4; np++) {
            int g = lane >> 3, lr = lane & 7;
            u32 a = tbase + TB
                  + (u32)(n0w + np * 16 + (g >> 1) * 8 + lr) * 80 + ks * 32 + (g & 1) * 16;
            u32 r4[4];
            ldm4(r4, a);
            bh[2 * np][0] = r4[0]; bh[2 * np][1] = r4[1];
            bh[2 * np + 1][0] = r4[2]; bh[2 * np + 1][1] = r4[3];
        }
        #pragma unroll
        for (int mi = 0; mi < 2; mi++)
            #pragma unroll
            for (int ni = 0; ni < 8; ni++)
                mma_fp(acc[mi][ni], aw[mi], bh[ni]);
    }
}

// ---------------- masks (+ atomic key init) ----------------
__global__ void detect_mask_kernel(const unsigned char* m) {
    __shared__ int flag;
    if (threadIdx.x == 0) flag = 0;
    __syncthreads();
    for (int i = threadIdx.x; i < BL_; i += blockDim.x)
        if ((i & 3) && m[i]) flag = 1;
    __syncthreads();
    if (threadIdx.x == 0) g_mask_is_byte = flag;
}
__global__ void build_mask_kernel(const void* m1, const void* m2) {
    int i = blockIdx.x * blockDim.x + threadIdx.x;
    if (i >= BL_) return;
    g_m1u[i] = 0u;
    g_m2u[i] = 0u;
    if (g_mask_is_byte) {
        g_mask1[i] = ((const unsigned char*)m1)[i] ? 1 : 0;
        g_mask2[i] = ((const unsigned char*)m2)[i] ? 1 : 0;
    } else {
        g_mask1[i] = ((const int*)m1)[i] ? 1 : 0;
        g_mask2[i] = ((const int*)m2)[i] ? 1 : 0;
    }
}

// ---------------- V transpose + fp16 convert ----------------
__global__ void __launch_bounds__(256) vsplit_kernel(
    const float* __restrict__ V1, const float* __restrict__ V2)
{
    __shared__ float ts[64][65];
    const int which = blockIdx.z & 1, b = blockIdx.z >> 1;
    const float* V = (which ? V2 : V1) + (size_t)b * L_ * D_;
    __half* dh = (which ? g_v2t : g_v1t) + (size_t)b * D_ * L_;
    const int i0 = blockIdx.x * 64, d0 = blockIdx.y * 64;
    const int tid = threadIdx.x;
    {
        const int r = tid >> 2, c0 = (tid & 3) * 16;
        #pragma unroll
        for (int j = 0; j < 4; j++) {
            float4 v = *(const float4*)&V[(size_t)(i0 + r) * D_ + d0 + c0 + 4 * j];
            ts[r][c0 + 4 * j] = v.x; ts[r][c0 + 4 * j + 1] = v.y;
            ts[r][c0 + 4 * j + 2] = v.z; ts[r][c0 + 4 * j + 3] = v.w;
        }
    }
    __syncthreads();
    {
        const int rd = tid >> 2, cw = (tid & 3) * 16;
        #pragma unroll
        for (int j = 0; j < 4; j++) {
            __half h[4];
            #pragma unroll
            for (int e = 0; e < 4; e++) h[e] = __float2half_rn(ts[cw + 4 * j + e][rd]);
            size_t o = (size_t)(d0 + rd) * L_ + i0 + cw + 4 * j;
            *(u64*)&dh[o] = pack4h(h[0], h[1], h[2], h[3]);
        }
    }
}

// ---------------- proj: relu(X W^T)(*scaling) -> bf16 hi/lo ----------------
__global__ void __launch_bounds__(256, 1) proj_kernel(
    const float* __restrict__ Q, const float* __restrict__ K,
    const float* __restrict__ Wq, const float* __restrict__ Wk,
    const float* __restrict__ scaling)
{
    extern __shared__ __align__(16) char smem[];
    const u32 sb = smem_u32(smem);
    const int tid = threadIdx.x, lane = tid & 31, w = tid >> 5;
    const int m0w = (w & 3) * 32, n0w = (w >> 2) * 64;
    const int which = blockIdx.y, row0 = blockIdx.x * 128;
    const float* X  = which ? K : Q;
    const float* Wm = which ? Wk : Wq;
    __nv_bfloat16* oh = which ? g_pk_hi : g_pq_hi;
    __nv_bfloat16* ol = which ? g_pk_lo : g_pq_lo;

    float acc[2][8][4];
    #pragma unroll
    for (int mi = 0; mi < 2; mi++)
        #pragma unroll
        for (int ni = 0; ni < 8; ni++)
            #pragma unroll
            for (int e = 0; e < 4; e++) acc[mi][ni][e] = 0.f;

    const int r_ = tid >> 1, hf = tid & 1;
    float4 xa[4], wb[4];

    auto ldchunk = [&](int c) {
        const int k0 = c * 32;
        const float* xr = X  + (size_t)(row0 + r_) * D_ + k0 + hf * 16;
        const float* wr = Wm + (size_t)r_ * D_ + k0 + hf * 16;
        #pragma unroll
        for (int j = 0; j < 4; j++) { xa[j] = *(const float4*)&xr[4 * j];
                                      wb[j] = *(const float4*)&wr[4 * j]; }
    };
    auto stchunk = [&](int buf) {
        char* tp = smem + TOFF + buf * STG4;
        const u32 off = (u32)r_ * 80 + hf * 32;
        #pragma unroll
        for (int j = 0; j < 4; j++) {
            __nv_bfloat16 h[4], l[4];
            split_bf(xa[j].x, h[0], l[0]); split_bf(xa[j].y, h[1], l[1]);
            split_bf(xa[j].z, h[2], l[2]); split_bf(xa[j].w, h[3], l[3]);
            *(u64*)(tp + off + j * 8)      = pack4(h[0], h[1], h[2], h[3]);
            *(u64*)(tp + TB + off + j * 8) = pack4(l[0], l[1], l[2], l[3]);
            split_bf(wb[j].x, h[0], l[0]); split_bf(wb[j].y, h[1], l[1]);
            split_bf(wb[j].z, h[2], l[2]); split_bf(wb[j].w, h[3], l[3]);
            *(u64*)(tp + 2 * TB + off + j * 8) = pack4(h[0], h[1], h[2], h[3]);
            *(u64*)(tp + 3 * TB + off + j * 8) = pack4(l[0], l[1], l[2], l[3]);
        }
    };

    ldchunk(0);
    stchunk(0);
    __syncthreads();
    for (int c = 0; c < 8; c++) {
        if (c + 1 < 8) ldchunk(c + 1);
        gemm_chunk(sb, c & 1, acc, lane, m0w, n0w);
        if (c + 1 < 8) stchunk((c + 1) & 1);
        __syncthreads();
    }

    #pragma unroll
    for (int mi = 0; mi < 2; mi++) {
        const int rr = row0 + m0w + mi * 16 + (lane >> 2);
        #pragma unroll
        for (int ni = 0; ni < 8; ni++) {
            const int cc = n0w + ni * 8 + 2 * (lane & 3);
            float s0 = 1.f, s1 = 1.f;
            if (which) { s0 = __ldg(&scaling[cc]); s1 = __ldg(&scaling[cc + 1]); }
            float v00 = fmaxf(acc[mi][ni][0], 0.f) * s0;
            float v01 = fmaxf(acc[mi][ni][1], 0.f) * s1;
            float v10 = fmaxf(acc[mi][ni][2], 0.f) * s0;
            float v11 = fmaxf(acc[mi][ni][3], 0.f) * s1;
            __nv_bfloat16 h0, l0, h1, l1;
            split_bf(v00, h0, l0); split_bf(v01, h1, l1);
            *(u32*)&oh[(size_t)rr * H_ + cc] = pack2(h0, h1);
            *(u32*)&ol[(size_t)rr * H_ + cc] = pack2(l0, l1);
            split_bf(v10, h0, l0); split_bf(v11, h1, l1);
            *(u32*)&oh[(size_t)(rr + 8) * H_ + cc] = pack2(h0, h1);
            *(u32*)&ol[(size_t)(rr + 8) * H_ + cc] = pack2(l0, l1);
        }
    }
}

// ---------------- scores: S = pq pk^T; stores S + row/col masked maxima ----------------
__global__ void __launch_bounds__(256, 1) scores_kernel()
{
    extern __shared__ __align__(16) char smem[];
    const u32 sb = smem_u32(smem);
    const int tid = threadIdx.x, lane = tid & 31, w = tid >> 5;
    const int m0w = (w & 3) * 32, n0w = (w >> 2) * 64;
    const int b = blockIdx.z, row0 = blockIdx.y * 128, col0 = blockIdx.x * 128;
    const __nv_bfloat16* aqh = g_pq_hi + (size_t)(b * L_ + row0) * H_;
    const __nv_bfloat16* aql = g_pq_lo + (size_t)(b * L_ + row0) * H_;
    const __nv_bfloat16* bkh = g_pk_hi + (size_t)(b * L_ + col0) * H_;
    const __nv_bfloat16* bkl = g_pk_lo + (size_t)(b * L_ + col0) * H_;
    float* S = g_S + (size_t)b * L_ * L_;

    float acc[2][8][4];
    #pragma unroll
    for (int mi = 0; mi < 2; mi++)
        #pragma unroll
        for (int ni = 0; ni < 8; ni++)
            #pragma unroll
            for (int e = 0; e < 4; e++) acc[mi][ni][e] = 0.f;

    auto cpAB = [&](int c, int stage) {
        const int k0 = c * 32;
        const u32 base = sb + TOFF + stage * STG4;
        #pragma unroll
        for (int t = 0; t < 2; t++) {
            int idx = tid + t * 256;
            int rr = idx >> 2, seg = idx & 3;
            u32 so = base + (u32)rr * 80 + seg * 16;
            size_t go = (size_t)rr * H_ + k0 + seg * 8;
            CPA16(so,          aqh + go);
            CPA16(so + TB,     aql + go);
            CPA16(so + 2 * TB, bkh + go);
            CPA16(so + 3 * TB, bkl + go);
        }
        CPA_COMMIT();
    };

    cpAB(0, 0); cpAB(1, 1); cpAB(2, 2); cpAB(3, 3);
    #pragma unroll
    for (int c = 0; c < 4; c++) {
        if      (c == 0) cpa_wait<3>();
        else if (c == 1) cpa_wait<2>();
        else if (c == 2) cpa_wait<1>();
        else             cpa_wait<0>();
        __syncthreads();
        gemm_chunk(sb, c, acc, lane, m0w, n0w);
    }

    // direct S stores
    #pragma unroll
    for (int mi = 0; mi < 2; mi++) {
        const int rr = m0w + mi * 16 + (lane >> 2);
        float* p0 = S + (size_t)(row0 + rr) * L_ + col0 + n0w + 2 * (lane & 3);
        #pragma unroll
        for (int ni = 0; ni < 8; ni++) {
            *(float2*)(p0 + ni * 8)          = make_float2(acc[mi][ni][0], acc[mi][ni][1]);
            *(float2*)(p0 + 8 * L_ + ni * 8) = make_float2(acc[mi][ni][2], acc[mi][ni][3]);
        }
    }

    // masked column max (mask over q rows) -> g_m2u
    {
        const unsigned char* mk2 = g_mask2 + (b << 11);
        float cmax[8][2];
        #pragma unroll
        for (int ni = 0; ni < 8; ni++) { cmax[ni][0] = -INFINITY; cmax[ni][1] = -INFINITY; }
        #pragma unroll
        for (int mi = 0; mi < 2; mi++) {
            const int rr = row0 + m0w + mi * 16 + (lane >> 2);
            const bool u0 = mk2[rr] == 0;
            const bool u1 = mk2[rr + 8] == 0;
            #pragma unroll
            for (int ni = 0; ni < 8; ni++) {
                if (u0) {
                    cmax[ni][0] = fmaxf(cmax[ni][0], acc[mi][ni][0]);
                    cmax[ni][1] = fmaxf(cmax[ni][1], acc[mi][ni][1]);
                }
                if (u1) {
                    cmax[ni][0] = fmaxf(cmax[ni][0], acc[mi][ni][2]);
                    cmax[ni][1] = fmaxf(cmax[ni][1], acc[mi][ni][3]);
                }
            }
        }
        #pragma unroll
        for (int off = 4; off <= 16; off <<= 1)
            #pragma unroll
            for (int ni = 0; ni < 8; ni++) {
                cmax[ni][0] = fmaxf(cmax[ni][0], __shfl_xor_sync(0xffffffffu, cmax[ni][0], off));
                cmax[ni][1] = fmaxf(cmax[ni][1], __shfl_xor_sync(0xffffffffu, cmax[ni][1], off));
            }
        if ((lane >> 2) == 0) {
            u32* mu = g_m2u + (b << 11) + col0 + n0w + 2 * (lane & 3);
            #pragma unroll
            for (int ni = 0; ni < 8; ni++) {
                atomicMax(&mu[ni * 8],     menc(cmax[ni][0]));
                atomicMax(&mu[ni * 8 + 1], menc(cmax[ni][1]));
            }
        }
    }

    // masked row max (mask over k cols) -> g_m1u
    {
        const unsigned char* mk1 = g_mask1 + (b << 11);
        const int cb = col0 + n0w + 2 * (lane & 3);
        float rmax[4] = { -INFINITY, -INFINITY, -INFINITY, -INFINITY };
        #pragma unroll
        for (int ni = 0; ni < 8; ni++) {
            const bool u0 = mk1[cb + ni * 8] == 0;
            const bool u1 = mk1[cb + ni * 8 + 1] == 0;
            #pragma unroll
            for (int mi = 0; mi < 2; mi++) {
                float v0 = u0 ? acc[mi][ni][0] : -INFINITY;
                float v1 = u1 ? acc[mi][ni][1] : -INFINITY;
                rmax[2 * mi] = fmaxf(rmax[2 * mi], fmaxf(v0, v1));
                float v2 = u0 ? acc[mi][ni][2] : -INFINITY;
                float v3 = u1 ? acc[mi][ni][3] : -INFINITY;
                rmax[2 * mi + 1] = fmaxf(rmax[2 * mi + 1], fmaxf(v2, v3));
            }
        }
        #pragma unroll
        for (int off = 1; off <= 2; off <<= 1)
            #pragma unroll
            for (int i = 0; i < 4; i++)
                rmax[i] = fmaxf(rmax[i], __shfl_xor_sync(0xffffffffu, rmax[i], off));
        if ((lane & 3) == 0) {
            u32* mu = g_m1u + (b << 11) + row0 + m0w + (lane >> 2);
            atomicMax(&mu[0],  menc(rmax[0]));
            atomicMax(&mu[8],  menc(rmax[1]));
            atomicMax(&mu[16], menc(rmax[2]));
            atomicMax(&mu[24], menc(rmax[3]));
        }
    }
}

// ---------------- weights: single S pass -> W1 + W2 + l partials ----------------
// CTA per (k-strip 64, q-part 512, b). Chunk = 64q x 64k staged in smem.
__global__ void __launch_bounds__(256) weights_kernel()
{
    extern __shared__ __align__(16) char smem[];
    const u32 sb = smem_u32(smem);
    const int strip = blockIdx.x, part = blockIdx.y, b = blockIdx.z;
    const int k0 = strip * 64, qbase = part * 512;
    const int tid = threadIdx.x;
    const float* Sb = g_S + (size_t)b * L_ * L_;
    __half* W1 = g_w1 + (size_t)b * L_ * L_;
    __half* W2 = g_w2 + (size_t)b * L_ * L_;

    float* m1s = (float*)(smem + W_M1S);
    float* m2s = (float*)(smem + W_M2S);
    float* lsm = (float*)(smem + W_LSM);
    float* tile = (float*)(smem + W_TILE);
    unsigned char* mk2s = (unsigned char*)(smem + W_MK2);
    unsigned char* mk1s = (unsigned char*)(smem + W_MK1);

    m1s[tid]       = mdec(g_m1u[(b << 11) + qbase + tid]);
    m1s[tid + 256] = mdec(g_m1u[(b << 11) + qbase + tid + 256]);
    if (tid < 64) {
        m2s[tid]  = mdec(g_m2u[(b << 11) + k0 + tid]);
        mk1s[tid] = g_mask1[(b << 11) + k0 + tid];
    }
    ((u32*)mk2s)[tid >> 1] = (tid & 1) ? ((u32*)mk2s)[tid >> 1]
                                       : ((const u32*)(g_mask2 + (b << 11) + qbase))[tid >> 1];
    // simpler/correct mask2 load:
    if (tid < 128) ((u32*)mk2s)[tid] = ((const u32*)(g_mask2 + (b << 11) + qbase))[tid];

    auto cpS = [&](int c, int buf) {
        const int q0 = qbase + c * 64;
        const u32 base = sb + buf * W_SBUF;
        #pragma unroll
        for (int t = 0; t < 4; t++) {
            int idx = tid + t * 256;
            int r = idx >> 4, seg = idx & 15;
            CPA16(base + (u32)r * (W_SROW * 4) + seg * 16,
                  Sb + (size_t)(q0 + r) * L_ + k0 + seg * 4);
        }
        CPA_COMMIT();
    };

    float l2reg = 0.f;
    const int kkB = tid & 63, qsB = tid >> 6;      // pass B mapping
    const int rrA = tid >> 2, segA = tid & 3;      // pass A / store mapping

    cpS(0, 0);
    cpS(1, 1);
    __syncthreads();   // mask/m smem ready (cp.async independent)

    for (int c = 0; c < 8; c++) {
        const int buf = c & 1;
        const int q0 = qbase + c * 64;
        if (c == 0) cpa_wait<1>(); else cpa_wait<1>();
        __syncthreads();
        const float* Ss = (const float*)(smem + buf * W_SBUF);

        // ---- pass A: W1 row-major + per-row partial sums ----
        {
            const float m = m1s[c * 64 + rrA];
            float lsum = 0.f;
            u32 pk[8];
            #pragma unroll
            for (int j = 0; j < 8; j++) {
                float s0 = Ss[rrA * W_SROW + segA * 16 + 2 * j];
                float s1 = Ss[rrA * W_SROW + segA * 16 + 2 * j + 1];
                float w0 = mk1s[segA * 16 + 2 * j]     ? 0.f : __expf(s0 - m);
                float w1 = mk1s[segA * 16 + 2 * j + 1] ? 0.f : __expf(s1 - m);
                lsum += w0 + w1;
                pk[j] = pack2h(__float2half_rn(w0), __float2half_rn(w1));
            }
            __half* wp = &W1[(size_t)(q0 + rrA) * L_ + k0 + segA * 16];
            *(uint4*)(wp)     = make_uint4(pk[0], pk[1], pk[2], pk[3]);
            *(uint4*)(wp + 8) = make_uint4(pk[4], pk[5], pk[6], pk[7]);
            lsm[tid] = lsum;
        }
        // ---- pass B: W2 column exp -> staged tile + per-col accumulation ----
        {
            const float m = m2s[kkB];
            #pragma unroll
            for (int j = 0; j < 16; j++) {
                float s = Ss[(qsB * 16 + j) * W_SROW + kkB];
                float wv = mk2s[c * 64 + qsB * 16 + j] ? 0.f : __expf(s - m);
                l2reg += wv;
                tile[kkB * W_TROW + qsB * 16 + j] = wv;
            }
        }
        __syncthreads();

        // ---- W2 store (transposed, coalesced) + l1 partial flush ----
        {
            u32 pk[8];
            #pragma unroll
            for (int j = 0; j < 8; j++) {
                float w0 = tile[rrA * W_TROW + segA * 16 + 2 * j];
                float w1 = tile[rrA * W_TROW + segA * 16 + 2 * j + 1];
                pk[j] = pack2h(__float2half_rn(w0), __float2half_rn(w1));
            }
            __half* wp = &W2[(size_t)(k0 + rrA) * L_ + q0 + segA * 16];
            *(uint4*)(wp)     = make_uint4(pk[0], pk[1], pk[2], pk[3]);
            *(uint4*)(wp + 8) = make_uint4(pk[4], pk[5], pk[6], pk[7]);
        }
        if (tid < 64)
            g_l1p[(size_t)strip * BL_ + (b << 11) + q0 + tid] =
                lsm[tid * 4] + lsm[tid * 4 + 1] + lsm[tid * 4 + 2] + lsm[tid * 4 + 3];
        __syncthreads();   // tile/lsm consumed before next pass writes

        if (c + 2 < 8) cpS(c + 2, buf);
    }

    // l2 partials: sum 4 q-groups per column
    lsm[tid] = l2reg;
    __syncthreads();
    if (tid < 64)
        g_l2p[(size_t)part * BL_ + (b << 11) + k0 + tid] =
            lsm[tid] + lsm[tid + 64] + lsm[tid + 128] + lsm[tid + 192];
}

// ---------------- branch: pure fp16 GEMM, 128x256 full-D tile, 512 thr ----------------
__global__ void __launch_bounds__(512, 1) branch_kernel(float* __restrict__ out)
{
    extern __shared__ __align__(16) char smem[];
    const u32 sb = smem_u32(smem);
    const int tid = threadIdx.x, lane = tid & 31, w = tid >> 5;
    const int m0w = (w & 3) * 32, n0w = (w >> 2) * 64;   // 16 warps: 4x4
    const int row0 = blockIdx.x * 128;
    const int br = blockIdx.z & 1, b = blockIdx.z >> 1;

    const __half* wf = (br ? g_w2 : g_w1) + (size_t)(b * L_ + row0) * L_;
    const __half* vt = (br ? g_v2t : g_v1t) + (size_t)b * D_ * L_;
    float* ob = out + (br ? (size_t)B_ * L_ * D_ : 0) + (size_t)(b * L_ + row0) * D_;

    float* s_sc = (float*)(smem);
    if (tid < 128) {
        const int idx = (b << 11) + row0 + tid;
        float l = 0.f;
        if (br) {
            #pragma unroll
            for (int p = 0; p < 4; p++) l += g_l2p[(size_t)p * BL_ + idx];
        } else {
            #pragma unroll
            for (int s = 0; s < 32; s++) l += g_l1p[(size_t)s * BL_ + idx];
        }
        s_sc[tid] = 1.f / l;
    }
    __syncthreads();

    float acc[2][8][4];
    #pragma unroll
    for (int mi = 0; mi < 2; mi++)
        #pragma unroll
        for (int ni = 0; ni < 8; ni++)
            #pragma unroll
            for (int e = 0; e < 4; e++) acc[mi][ni][e] = 0.f;

    auto cpc = [&](int c, int stage) {
        const int i0 = c * 32;
        const u32 base = sb + TOFF + stage * BSTG;
        {
            int rr = tid >> 2, seg = tid & 3;
            CPA16(base + (u32)rr * 80 + seg * 16, wf + (size_t)rr * L_ + i0 + seg * 8);
        }
        #pragma unroll
        for (int t = 0; t < 2; t++) {
            int idx = tid + t * 512;
            int rr = idx >> 2, seg = idx & 3;
            CPA16(base + TB + (u32)rr * 80 + seg * 16, vt + (size_t)rr * L_ + i0 + seg * 8);
        }
    };

    cpc(0, 0); CPA_COMMIT();
    cpc(1, 1); CPA_COMMIT();
    cpc(2, 2); CPA_COMMIT();
    cpc(3, 3); CPA_COMMIT();

    for (int c = 0; c < 64; c++) {
        cpa_wait<3>();
        __syncthreads();
        gemm_chunk_f16(sb, c & 3, acc, lane, m0w, n0w);
        __syncthreads();
        if (c + 4 < 64) cpc(c + 4, (c + 4) & 3);
        CPA_COMMIT();
    }

    #pragma unroll
    for (int mi = 0; mi < 2; mi++) {
        const int rr = m0w + mi * 16 + (lane >> 2);
        const float sc0 = s_sc[rr], sc1 = s_sc[rr + 8];
        float* p0 = ob + (size_t)rr * D_ + n0w + 2 * (lane & 3);
        float* p1 = p0 + 8 * D_;
        #pragma unroll
        for (int ni = 0; ni < 8; ni++) {
            *(float2*)(p0 + ni * 8) = make_float2(acc[mi][ni][0] * sc0, acc[mi][ni][1] * sc0);
            *(float2*)(p1 + ni * 8) = make_float2(acc[mi][ni][2] * sc1, acc[mi][ni][3] * sc1);
        }
    }
}

// ---------------------------------------------------------------------------
extern "C" void kernel_launch(void* const* d_in, const int* in_sizes, int n_in,
                              void* d_out, int out_size)
{
    const float* queries = (const float*)d_in[0];
    const float* keys    = (const float*)d_in[1];
    const float* values1 = (const float*)d_in[2];
    const void*  mask1   = d_in[3];
    const float* values2 = (const float*)d_in[4];
    const void*  mask2   = d_in[5];
    const float* Wq      = (const float*)d_in[6];
    const float* Wk      = (const float*)d_in[7];
    const float* scaling = (const float*)d_in[8];
    float* out = (float*)d_out;

    cudaFuncSetAttribute(proj_kernel,    cudaFuncAttributeMaxDynamicSharedMemorySize, PSMEM);
    cudaFuncSetAttribute(scores_kernel,  cudaFuncAttributeMaxDynamicSharedMemorySize, SSMEM);
    cudaFuncSetAttribute(weights_kernel, cudaFuncAttributeMaxDynamicSharedMemorySize, WSMEM);
    cudaFuncSetAttribute(branch_kernel,  cudaFuncAttributeMaxDynamicSharedMemorySize, BSMEM);

    detect_mask_kernel<<<1, 256>>>((const unsigned char*)mask1);
    build_mask_kernel<<<(BL_ + 255) / 256, 256>>>(mask1, mask2);

    vsplit_kernel<<<dim3(L_ / 64, D_ / 64, B_ * 2), 256>>>(values1, values2);

    proj_kernel<<<dim3((B_ * L_) / 128, 2), 256, PSMEM>>>(queries, keys, Wq, Wk, scaling);

    scores_kernel<<<dim3(L_ / 128, L_ / 128, B_), 256, SSMEM>>>();

    weights_kernel<<<dim3(32, 4, B_), 256, WSMEM>>>();

    branch_kernel<<<dim3(L_ / 128, 1, B_ * 2), 512, BSMEM>>>(out);
}

// round 14
// speedup vs baseline: 1.1478x; 1.0357x over previous
#include <cuda_runtime.h>
#include <cuda_bf16.h>
#include <cuda_fp16.h>
#include <math.h>

#define B_  8
#define L_  2048
#define D_  256
#define H_  128
#define BL_ (B_ * L_)

typedef unsigned int u32;
typedef unsigned long long u64;

// ---------------- device scratch ----------------
__device__ __align__(16) float g_S [(size_t)B_ * L_ * L_];     // [b][q][k]
__device__ __align__(16) __half g_w1[(size_t)B_ * L_ * L_];    // weights br1 [b][q][k]
__device__ __align__(16) __half g_w2[(size_t)B_ * L_ * L_];    // weights br2 [b][k][q]
__device__ __align__(16) __half g_pq_hi[(size_t)B_ * L_ * H_]; // fp16 hi/lo pq
__device__ __align__(16) __half g_pq_lo[(size_t)B_ * L_ * H_];
__device__ __align__(16) __half g_pk   [(size_t)B_ * L_ * H_]; // fp16 pk (single)
__device__ __align__(16) __half g_v1t[(size_t)B_ * D_ * L_];   // V^T fp16 [b][d][k]
__device__ __align__(16) __half g_v2t[(size_t)B_ * D_ * L_];   // V^T fp16 [b][d][q]
__device__ u32 g_m1u[BL_];                // row max (branch1), monotone keys
__device__ u32 g_m2u[BL_];                // col max (branch2), monotone keys
__device__ float g_l1p[32 * BL_];         // per-k-strip partial row sums
__device__ float g_l2p[4 * BL_];          // per-q-part partial col sums
__device__ unsigned char g_mask1[BL_];
__device__ unsigned char g_mask2[BL_];
__device__ int g_mask_is_byte;

// ---------------- PTX helpers ----------------
__device__ __forceinline__ u32 smem_u32(const void* p) {
    u32 a;
    asm("{ .reg .u64 t; cvta.to.shared.u64 t, %1; cvt.u32.u64 %0, t; }" : "=r"(a) : "l"(p));
    return a;
}
__device__ __forceinline__ void ldm4(u32* r, u32 addr) {
    asm volatile("ldmatrix.sync.aligned.m8n8.x4.shared.b16 {%0,%1,%2,%3}, [%4];"
        : "=r"(r[0]), "=r"(r[1]), "=r"(r[2]), "=r"(r[3]) : "r"(addr));
}
__device__ __forceinline__ void mma_bf(float* c, const u32* a, const u32* b) {
    asm volatile("mma.sync.aligned.m16n8k16.row.col.f32.bf16.bf16.f32 "
        "{%0,%1,%2,%3}, {%4,%5,%6,%7}, {%8,%9}, {%0,%1,%2,%3};"
        : "+f"(c[0]), "+f"(c[1]), "+f"(c[2]), "+f"(c[3])
        : "r"(a[0]), "r"(a[1]), "r"(a[2]), "r"(a[3]), "r"(b[0]), "r"(b[1]));
}
__device__ __forceinline__ void mma_fp(float* c, const u32* a, const u32* b) {
    asm volatile("mma.sync.aligned.m16n8k16.row.col.f32.f16.f16.f32 "
        "{%0,%1,%2,%3}, {%4,%5,%6,%7}, {%8,%9}, {%0,%1,%2,%3};"
        : "+f"(c[0]), "+f"(c[1]), "+f"(c[2]), "+f"(c[3])
        : "r"(a[0]), "r"(a[1]), "r"(a[2]), "r"(a[3]), "r"(b[0]), "r"(b[1]));
}
#define CPA16(sm, gp)  asm volatile("cp.async.ca.shared.global [%0], [%1], 16;" :: "r"(sm), "l"(gp))
#define CPA_COMMIT()   asm volatile("cp.async.commit_group;" ::: "memory")
template<int N> __device__ __forceinline__ void cpa_wait() {
    asm volatile("cp.async.wait_group %0;" :: "n"(N) : "memory");
}

__device__ __forceinline__ void split_bf(float v, __nv_bfloat16& h, __nv_bfloat16& l) {
    h = __float2bfloat16_rn(v);
    l = __float2bfloat16_rn(v - __bfloat162float(h));
}
__device__ __forceinline__ void split_hf(float v, __half& h, __half& l) {
    h = __float2half_rn(v);
    l = __float2half_rn(v - __half2float(h));
}
__device__ __forceinline__ u64 pack4(__nv_bfloat16 a, __nv_bfloat16 b,
                                     __nv_bfloat16 c, __nv_bfloat16 d) {
    union { __nv_bfloat16 h[4]; u64 u; } x;
    x.h[0] = a; x.h[1] = b; x.h[2] = c; x.h[3] = d;
    return x.u;
}
__device__ __forceinline__ u64 pack4h(__half a, __half b, __half c, __half d) {
    union { __half h[4]; u64 u; } x;
    x.h[0] = a; x.h[1] = b; x.h[2] = c; x.h[3] = d;
    return x.u;
}
__device__ __forceinline__ u32 pack2h(__half a, __half b) {
    union { __half h[2]; u32 u; } x;
    x.h[0] = a; x.h[1] = b;
    return x.u;
}
// monotone float<->uint for atomicMax
__device__ __forceinline__ u32 menc(float f) {
    u32 b = __float_as_uint(f);
    return (b & 0x80000000u) ? ~b : (b | 0x80000000u);
}
__device__ __forceinline__ float mdec(u32 k) {
    u32 b = (k & 0x80000000u) ? (k ^ 0x80000000u) : ~k;
    return __uint_as_float(b);
}

// tile geometry: rows x 32 halves, padded row stride 80B
#define TB    10240                  // 128 rows x 80B
#define STG4  (4 * TB)               // proj stage: Ah|Al|Bh|Bl
#define STG3  (3 * TB)               // scores stage: Ah|Al|B
#define TOFF  1024
#define SSMEM (TOFF + 4 * STG3)      // scores 4-stage: 123904
#define PSMEM (TOFF + 2 * STG4)      // proj double buffer: 82944
#define BSTG  (3 * TB)               // branch stage: A(128) | B(256)
#define BSMEM (TOFF + 4 * BSTG)      // 123904

// weights kernel smem layout (dynamic)
#define W_SROW   68
#define W_SBUF   (64 * W_SROW * 4)
#define W_TILE   (2 * W_SBUF)
#define W_TROW   69
#define W_LSM    (W_TILE + 64 * W_TROW * 4)
#define W_M1S    (W_LSM + 1024)
#define W_M2S    (W_M1S + 2048)
#define W_MK2    (W_M2S + 256)
#define W_MK1    (W_MK2 + 512)
#define WSMEM    (W_MK1 + 64)

// bf16x3 chunk (proj): 8 warps, warp tile 32x64 over 128x128
__device__ __forceinline__ void gemm_chunk(u32 sb, int stage, float (&acc)[2][8][4],
                                           int lane, int m0w, int n0w)
{
    const u32 tbase = sb + TOFF + stage * STG4;
    #pragma unroll
    for (int ks = 0; ks < 2; ks++) {
        u32 ah[2][4], al[2][4];
        #pragma unroll
        for (int mi = 0; mi < 2; mi++) {
            u32 a = tbase + (u32)(m0w + mi * 16 + (lane & 15)) * 80 + ks * 32 + (lane >> 4) * 16;
            ldm4(ah[mi], a);
            ldm4(al[mi], a + TB);
        }
        u32 bh[8][2], bl[8][2];
        #pragma unroll
        for (int np = 0; np < 4; np++) {
            int g = lane >> 3, lr = lane & 7;
            u32 a = tbase + 2 * TB
                  + (u32)(n0w + np * 16 + (g >> 1) * 8 + lr) * 80 + ks * 32 + (g & 1) * 16;
            u32 r4[4];
            ldm4(r4, a);
            bh[2 * np][0] = r4[0]; bh[2 * np][1] = r4[1];
            bh[2 * np + 1][0] = r4[2]; bh[2 * np + 1][1] = r4[3];
            ldm4(r4, a + TB);
            bl[2 * np][0] = r4[0]; bl[2 * np][1] = r4[1];
            bl[2 * np + 1][0] = r4[2]; bl[2 * np + 1][1] = r4[3];
        }
        #pragma unroll
        for (int mi = 0; mi < 2; mi++)
            #pragma unroll
            for (int ni = 0; ni < 8; ni++) {
                mma_bf(acc[mi][ni], ah[mi], bh[ni]);
                mma_bf(acc[mi][ni], ah[mi], bl[ni]);
                mma_bf(acc[mi][ni], al[mi], bh[ni]);
            }
    }
}

// fp16 2-MMA chunk (scores): A hi/lo pair, single B. 8 warps over 128x128.
__device__ __forceinline__ void gemm_chunk_s(u32 sb, int stage, float (&acc)[2][8][4],
                                             int lane, int m0w, int n0w)
{
    const u32 tbase = sb + TOFF + stage * STG3;
    #pragma unroll
    for (int ks = 0; ks < 2; ks++) {
        u32 ah[2][4], al[2][4];
        #pragma unroll
        for (int mi = 0; mi < 2; mi++) {
            u32 a = tbase + (u32)(m0w + mi * 16 + (lane & 15)) * 80 + ks * 32 + (lane >> 4) * 16;
            ldm4(ah[mi], a);
            ldm4(al[mi], a + TB);
        }
        u32 bh[8][2];
        #pragma unroll
        for (int np = 0; np < 4; np++) {
            int g = lane >> 3, lr = lane & 7;
            u32 a = tbase + 2 * TB
                  + (u32)(n0w + np * 16 + (g >> 1) * 8 + lr) * 80 + ks * 32 + (g & 1) * 16;
            u32 r4[4];
            ldm4(r4, a);
            bh[2 * np][0] = r4[0]; bh[2 * np][1] = r4[1];
            bh[2 * np + 1][0] = r4[2]; bh[2 * np + 1][1] = r4[3];
        }
        #pragma unroll
        for (int mi = 0; mi < 2; mi++)
            #pragma unroll
            for (int ni = 0; ni < 8; ni++) {
                mma_fp(acc[mi][ni], ah[mi], bh[ni]);
                mma_fp(acc[mi][ni], al[mi], bh[ni]);
            }
    }
}

// fp16 single-MMA chunk (branch): 16 warps, warp tile 32x64 over 128x256
__device__ __forceinline__ void gemm_chunk_f16(u32 sb, int stage, float (&acc)[2][8][4],
                                               int lane, int m0w, int n0w)
{
    const u32 tbase = sb + TOFF + stage * BSTG;
    #pragma unroll
    for (int ks = 0; ks < 2; ks++) {
        u32 aw[2][4];
        #pragma unroll
        for (int mi = 0; mi < 2; mi++) {
            u32 a = tbase + (u32)(m0w + mi * 16 + (lane & 15)) * 80 + ks * 32 + (lane >> 4) * 16;
            ldm4(aw[mi], a);
        }
        u32 bh[8][2];
        #pragma unroll
        for (int np = 0; np < 4; np++) {
            int g = lane >> 3, lr = lane & 7;
            u32 a = tbase + TB
                  + (u32)(n0w + np * 16 + (g >> 1) * 8 + lr) * 80 + ks * 32 + (g & 1) * 16;
            u32 r4[4];
            ldm4(r4, a);
            bh[2 * np][0] = r4[0]; bh[2 * np][1] = r4[1];
            bh[2 * np + 1][0] = r4[2]; bh[2 * np + 1][1] = r4[3];
        }
        #pragma unroll
        for (int mi = 0; mi < 2; mi++)
            #pragma unroll
            for (int ni = 0; ni < 8; ni++)
                mma_fp(acc[mi][ni], aw[mi], bh[ni]);
    }
}

// ---------------- masks (+ atomic key init) ----------------
__global__ void detect_mask_kernel(const unsigned char* m) {
    __shared__ int flag;
    if (threadIdx.x == 0) flag = 0;
    __syncthreads();
    for (int i = threadIdx.x; i < BL_; i += blockDim.x)
        if ((i & 3) && m[i]) flag = 1;
    __syncthreads();
    if (threadIdx.x == 0) g_mask_is_byte = flag;
}
__global__ void build_mask_kernel(const void* m1, const void* m2) {
    int i = blockIdx.x * blockDim.x + threadIdx.x;
    if (i >= BL_) return;
    g_m1u[i] = 0u;
    g_m2u[i] = 0u;
    if (g_mask_is_byte) {
        g_mask1[i] = ((const unsigned char*)m1)[i] ? 1 : 0;
        g_mask2[i] = ((const unsigned char*)m2)[i] ? 1 : 0;
    } else {
        g_mask1[i] = ((const int*)m1)[i] ? 1 : 0;
        g_mask2[i] = ((const int*)m2)[i] ? 1 : 0;
    }
}

// ---------------- pre: proj (blocks 0..255) + vsplit (blocks 256..2303) ----------------
__global__ void __launch_bounds__(256, 1) pre_kernel(
    const float* __restrict__ Q, const float* __restrict__ K,
    const float* __restrict__ Wq, const float* __restrict__ Wk,
    const float* __restrict__ scaling,
    const float* __restrict__ V1, const float* __restrict__ V2)
{
    extern __shared__ __align__(16) char smem[];
    const int tid = threadIdx.x;

    if (blockIdx.x >= 256) {
        // ---------- vsplit part: V transpose + fp16 convert ----------
        const int vb = blockIdx.x - 256;          // 0..2047
        const int i0 = (vb & 31) * 64;
        const int d0 = ((vb >> 5) & 3) * 64;
        const int z = vb >> 7;
        const int which = z & 1, b = z >> 1;
        const float* V = (which ? V2 : V1) + (size_t)b * L_ * D_;
        __half* dh = (which ? g_v2t : g_v1t) + (size_t)b * D_ * L_;
        float* ts = (float*)smem;                 // [64][65]
        {
            const int r = tid >> 2, c0 = (tid & 3) * 16;
            #pragma unroll
            for (int j = 0; j < 4; j++) {
                float4 v = *(const float4*)&V[(size_t)(i0 + r) * D_ + d0 + c0 + 4 * j];
                ts[r * 65 + c0 + 4 * j]     = v.x;
                ts[r * 65 + c0 + 4 * j + 1] = v.y;
                ts[r * 65 + c0 + 4 * j + 2] = v.z;
                ts[r * 65 + c0 + 4 * j + 3] = v.w;
            }
        }
        __syncthreads();
        {
            const int rd = tid >> 2, cw = (tid & 3) * 16;
            #pragma unroll
            for (int j = 0; j < 4; j++) {
                __half h[4];
                #pragma unroll
                for (int e = 0; e < 4; e++)
                    h[e] = __float2half_rn(ts[(cw + 4 * j + e) * 65 + rd]);
                size_t o = (size_t)(d0 + rd) * L_ + i0 + cw + 4 * j;
                *(u64*)&dh[o] = pack4h(h[0], h[1], h[2], h[3]);
            }
        }
        return;
    }

    // ---------- proj part: relu(X W^T)(*scaling) -> pq fp16 hi/lo, pk fp16 ----------
    const u32 sb = smem_u32(smem);
    const int lane = tid & 31, w = tid >> 5;
    const int m0w = (w & 3) * 32, n0w = (w >> 2) * 64;
    const int pbid = blockIdx.x;
    const int which = pbid >> 7, row0 = (pbid & 127) * 128;
    const float* X  = which ? K : Q;
    const float* Wm = which ? Wk : Wq;

    float acc[2][8][4];
    #pragma unroll
    for (int mi = 0; mi < 2; mi++)
        #pragma unroll
        for (int ni = 0; ni < 8; ni++)
            #pragma unroll
            for (int e = 0; e < 4; e++) acc[mi][ni][e] = 0.f;

    const int r_ = tid >> 1, hf = tid & 1;
    float4 xa[4], wb[4];

    auto ldchunk = [&](int c) {
        const int k0 = c * 32;
        const float* xr = X  + (size_t)(row0 + r_) * D_ + k0 + hf * 16;
        const float* wr = Wm + (size_t)r_ * D_ + k0 + hf * 16;
        #pragma unroll
        for (int j = 0; j < 4; j++) { xa[j] = *(const float4*)&xr[4 * j];
                                      wb[j] = *(const float4*)&wr[4 * j]; }
    };
    auto stchunk = [&](int buf) {
        char* tp = smem + TOFF + buf * STG4;
        const u32 off = (u32)r_ * 80 + hf * 32;
        #pragma unroll
        for (int j = 0; j < 4; j++) {
            __nv_bfloat16 h[4], l[4];
            split_bf(xa[j].x, h[0], l[0]); split_bf(xa[j].y, h[1], l[1]);
            split_bf(xa[j].z, h[2], l[2]); split_bf(xa[j].w, h[3], l[3]);
            *(u64*)(tp + off + j * 8)      = pack4(h[0], h[1], h[2], h[3]);
            *(u64*)(tp + TB + off + j * 8) = pack4(l[0], l[1], l[2], l[3]);
            split_bf(wb[j].x, h[0], l[0]); split_bf(wb[j].y, h[1], l[1]);
            split_bf(wb[j].z, h[2], l[2]); split_bf(wb[j].w, h[3], l[3]);
            *(u64*)(tp + 2 * TB + off + j * 8) = pack4(h[0], h[1], h[2], h[3]);
            *(u64*)(tp + 3 * TB + off + j * 8) = pack4(l[0], l[1], l[2], l[3]);
        }
    };

    ldchunk(0);
    stchunk(0);
    __syncthreads();
    for (int c = 0; c < 8; c++) {
        if (c + 1 < 8) ldchunk(c + 1);
        gemm_chunk(sb, c & 1, acc, lane, m0w, n0w);
        if (c + 1 < 8) stchunk((c + 1) & 1);
        __syncthreads();
    }

    #pragma unroll
    for (int mi = 0; mi < 2; mi++) {
        const int rr = row0 + m0w + mi * 16 + (lane >> 2);
        #pragma unroll
        for (int ni = 0; ni < 8; ni++) {
            const int cc = n0w + ni * 8 + 2 * (lane & 3);
            float s0 = 1.f, s1 = 1.f;
            if (which) { s0 = __ldg(&scaling[cc]); s1 = __ldg(&scaling[cc + 1]); }
            float v00 = fmaxf(acc[mi][ni][0], 0.f) * s0;
            float v01 = fmaxf(acc[mi][ni][1], 0.f) * s1;
            float v10 = fmaxf(acc[mi][ni][2], 0.f) * s0;
            float v11 = fmaxf(acc[mi][ni][3], 0.f) * s1;
            if (which) {
                *(u32*)&g_pk[(size_t)rr * H_ + cc] =
                    pack2h(__float2half_rn(v00), __float2half_rn(v01));
                *(u32*)&g_pk[(size_t)(rr + 8) * H_ + cc] =
                    pack2h(__float2half_rn(v10), __float2half_rn(v11));
            } else {
                __half h0, l0, h1, l1;
                split_hf(v00, h0, l0); split_hf(v01, h1, l1);
                *(u32*)&g_pq_hi[(size_t)rr * H_ + cc] = pack2h(h0, h1);
                *(u32*)&g_pq_lo[(size_t)rr * H_ + cc] = pack2h(l0, l1);
                split_hf(v10, h0, l0); split_hf(v11, h1, l1);
                *(u32*)&g_pq_hi[(size_t)(rr + 8) * H_ + cc] = pack2h(h0, h1);
                *(u32*)&g_pq_lo[(size_t)(rr + 8) * H_ + cc] = pack2h(l0, l1);
            }
        }
    }
}

// ---------------- scores: S = pq pk^T (fp16 2-MMA); S + row/col maxima ----------------
__global__ void __launch_bounds__(256, 1) scores_kernel()
{
    extern __shared__ __align__(16) char smem[];
    const u32 sb = smem_u32(smem);
    const int tid = threadIdx.x, lane = tid & 31, w = tid >> 5;
    const int m0w = (w & 3) * 32, n0w = (w >> 2) * 64;
    const int b = blockIdx.z, row0 = blockIdx.y * 128, col0 = blockIdx.x * 128;
    const __half* aqh = g_pq_hi + (size_t)(b * L_ + row0) * H_;
    const __half* aql = g_pq_lo + (size_t)(b * L_ + row0) * H_;
    const __half* bk  = g_pk    + (size_t)(b * L_ + col0) * H_;
    float* S = g_S + (size_t)b * L_ * L_;

    float acc[2][8][4];
    #pragma unroll
    for (int mi = 0; mi < 2; mi++)
        #pragma unroll
        for (int ni = 0; ni < 8; ni++)
            #pragma unroll
            for (int e = 0; e < 4; e++) acc[mi][ni][e] = 0.f;

    auto cpAB = [&](int c, int stage) {
        const int k0 = c * 32;
        const u32 base = sb + TOFF + stage * STG3;
        #pragma unroll
        for (int t = 0; t < 2; t++) {
            int idx = tid + t * 256;
            int rr = idx >> 2, seg = idx & 3;
            u32 so = base + (u32)rr * 80 + seg * 16;
            size_t go = (size_t)rr * H_ + k0 + seg * 8;
            CPA16(so,          aqh + go);
            CPA16(so + TB,     aql + go);
            CPA16(so + 2 * TB, bk + go);
        }
        CPA_COMMIT();
    };

    cpAB(0, 0); cpAB(1, 1); cpAB(2, 2); cpAB(3, 3);
    #pragma unroll
    for (int c = 0; c < 4; c++) {
        if      (c == 0) cpa_wait<3>();
        else if (c == 1) cpa_wait<2>();
        else if (c == 2) cpa_wait<1>();
        else             cpa_wait<0>();
        __syncthreads();
        gemm_chunk_s(sb, c, acc, lane, m0w, n0w);
    }

    // direct S stores
    #pragma unroll
    for (int mi = 0; mi < 2; mi++) {
        const int rr = m0w + mi * 16 + (lane >> 2);
        float* p0 = S + (size_t)(row0 + rr) * L_ + col0 + n0w + 2 * (lane & 3);
        #pragma unroll
        for (int ni = 0; ni < 8; ni++) {
            *(float2*)(p0 + ni * 8)          = make_float2(acc[mi][ni][0], acc[mi][ni][1]);
            *(float2*)(p0 + 8 * L_ + ni * 8) = make_float2(acc[mi][ni][2], acc[mi][ni][3]);
        }
    }

    // masked column max (mask over q rows) -> g_m2u
    {
        const unsigned char* mk2 = g_mask2 + (b << 11);
        float cmax[8][2];
        #pragma unroll
        for (int ni = 0; ni < 8; ni++) { cmax[ni][0] = -INFINITY; cmax[ni][1] = -INFINITY; }
        #pragma unroll
        for (int mi = 0; mi < 2; mi++) {
            const int rr = row0 + m0w + mi * 16 + (lane >> 2);
            const bool u0 = mk2[rr] == 0;
            const bool u1 = mk2[rr + 8] == 0;
            #pragma unroll
            for (int ni = 0; ni < 8; ni++) {
                if (u0) {
                    cmax[ni][0] = fmaxf(cmax[ni][0], acc[mi][ni][0]);
                    cmax[ni][1] = fmaxf(cmax[ni][1], acc[mi][ni][1]);
                }
                if (u1) {
                    cmax[ni][0] = fmaxf(cmax[ni][0], acc[mi][ni][2]);
                    cmax[ni][1] = fmaxf(cmax[ni][1], acc[mi][ni][3]);
                }
            }
        }
        #pragma unroll
        for (int off = 4; off <= 16; off <<= 1)
            #pragma unroll
            for (int ni = 0; ni < 8; ni++) {
                cmax[ni][0] = fmaxf(cmax[ni][0], __shfl_xor_sync(0xffffffffu, cmax[ni][0], off));
                cmax[ni][1] = fmaxf(cmax[ni][1], __shfl_xor_sync(0xffffffffu, cmax[ni][1], off));
            }
        if ((lane >> 2) == 0) {
            u32* mu = g_m2u + (b << 11) + col0 + n0w + 2 * (lane & 3);
            #pragma unroll
            for (int ni = 0; ni < 8; ni++) {
                atomicMax(&mu[ni * 8],     menc(cmax[ni][0]));
                atomicMax(&mu[ni * 8 + 1], menc(cmax[ni][1]));
            }
        }
    }

    // masked row max (mask over k cols) -> g_m1u
    {
        const unsigned char* mk1 = g_mask1 + (b << 11);
        const int cb = col0 + n0w + 2 * (lane & 3);
        float rmax[4] = { -INFINITY, -INFINITY, -INFINITY, -INFINITY };
        #pragma unroll
        for (int ni = 0; ni < 8; ni++) {
            const bool u0 = mk1[cb + ni * 8] == 0;
            const bool u1 = mk1[cb + ni * 8 + 1] == 0;
            #pragma unroll
            for (int mi = 0; mi < 2; mi++) {
                float v0 = u0 ? acc[mi][ni][0] : -INFINITY;
                float v1 = u1 ? acc[mi][ni][1] : -INFINITY;
                rmax[2 * mi] = fmaxf(rmax[2 * mi], fmaxf(v0, v1));
                float v2 = u0 ? acc[mi][ni][2] : -INFINITY;
                float v3 = u1 ? acc[mi][ni][3] : -INFINITY;
                rmax[2 * mi + 1] = fmaxf(rmax[2 * mi + 1], fmaxf(v2, v3));
            }
        }
        #pragma unroll
        for (int off = 1; off <= 2; off <<= 1)
            #pragma unroll
            for (int i = 0; i < 4; i++)
                rmax[i] = fmaxf(rmax[i], __shfl_xor_sync(0xffffffffu, rmax[i], off));
        if ((lane & 3) == 0) {
            u32* mu = g_m1u + (b << 11) + row0 + m0w + (lane >> 2);
            atomicMax(&mu[0],  menc(rmax[0]));
            atomicMax(&mu[8],  menc(rmax[1]));
            atomicMax(&mu[16], menc(rmax[2]));
            atomicMax(&mu[24], menc(rmax[3]));
        }
    }
}

// ---------------- weights: single S pass -> W1 + W2 + l partials ----------------
__global__ void __launch_bounds__(256) weights_kernel()
{
    extern __shared__ __align__(16) char smem[];
    const u32 sb = smem_u32(smem);
    const int strip = blockIdx.x, part = blockIdx.y, b = blockIdx.z;
    const int k0 = strip * 64, qbase = part * 512;
    const int tid = threadIdx.x;
    const float* Sb = g_S + (size_t)b * L_ * L_;
    __half* W1 = g_w1 + (size_t)b * L_ * L_;
    __half* W2 = g_w2 + (size_t)b * L_ * L_;

    float* m1s = (float*)(smem + W_M1S);
    float* m2s = (float*)(smem + W_M2S);
    float* lsm = (float*)(smem + W_LSM);
    float* tile = (float*)(smem + W_TILE);
    unsigned char* mk2s = (unsigned char*)(smem + W_MK2);
    unsigned char* mk1s = (unsigned char*)(smem + W_MK1);

    m1s[tid]       = mdec(g_m1u[(b << 11) + qbase + tid]);
    m1s[tid + 256] = mdec(g_m1u[(b << 11) + qbase + tid + 256]);
    if (tid < 64) {
        m2s[tid]  = mdec(g_m2u[(b << 11) + k0 + tid]);
        mk1s[tid] = g_mask1[(b << 11) + k0 + tid];
    }
    if (tid < 128) ((u32*)mk2s)[tid] = ((const u32*)(g_mask2 + (b << 11) + qbase))[tid];

    auto cpS = [&](int c, int buf) {
        const int q0 = qbase + c * 64;
        const u32 base = sb + buf * W_SBUF;
        #pragma unroll
        for (int t = 0; t < 4; t++) {
            int idx = tid + t * 256;
            int r = idx >> 4, seg = idx & 15;
            CPA16(base + (u32)r * (W_SROW * 4) + seg * 16,
                  Sb + (size_t)(q0 + r) * L_ + k0 + seg * 4);
        }
        CPA_COMMIT();
    };

    float l2reg = 0.f;
    const int kkB = tid & 63, qsB = tid >> 6;
    const int rrA = tid >> 2, segA = tid & 3;

    cpS(0, 0);
    cpS(1, 1);
    __syncthreads();

    for (int c = 0; c < 8; c++) {
        const int buf = c & 1;
        const int q0 = qbase + c * 64;
        cpa_wait<1>();
        __syncthreads();
        const float* Ss = (const float*)(smem + buf * W_SBUF);

        {   // pass A: W1 row-major + per-row partial sums
            const float m = m1s[c * 64 + rrA];
            float lsum = 0.f;
            u32 pk[8];
            #pragma unroll
            for (int j = 0; j < 8; j++) {
                float s0 = Ss[rrA * W_SROW + segA * 16 + 2 * j];
                float s1 = Ss[rrA * W_SROW + segA * 16 + 2 * j + 1];
                float w0 = mk1s[segA * 16 + 2 * j]     ? 0.f : __expf(s0 - m);
                float w1 = mk1s[segA * 16 + 2 * j + 1] ? 0.f : __expf(s1 - m);
                lsum += w0 + w1;
                pk[j] = pack2h(__float2half_rn(w0), __float2half_rn(w1));
            }
            __half* wp = &W1[(size_t)(q0 + rrA) * L_ + k0 + segA * 16];
            *(uint4*)(wp)     = make_uint4(pk[0], pk[1], pk[2], pk[3]);
            *(uint4*)(wp + 8) = make_uint4(pk[4], pk[5], pk[6], pk[7]);
            lsm[tid] = lsum;
        }
        {   // pass B: W2 column exp -> staged tile + per-col accumulation
            const float m = m2s[kkB];
            #pragma unroll
            for (int j = 0; j < 16; j++) {
                float s = Ss[(qsB * 16 + j) * W_SROW + kkB];
                float wv = mk2s[c * 64 + qsB * 16 + j] ? 0.f : __expf(s - m);
                l2reg += wv;
                tile[kkB * W_TROW + qsB * 16 + j] = wv;
            }
        }
        __syncthreads();

        {   // W2 transposed store + l1 partial flush
            u32 pk[8];
            #pragma unroll
            for (int j = 0; j < 8; j++) {
                float w0 = tile[rrA * W_TROW + segA * 16 + 2 * j];
                float w1 = tile[rrA * W_TROW + segA * 16 + 2 * j + 1];
                pk[j] = pack2h(__float2half_rn(w0), __float2half_rn(w1));
            }
            __half* wp = &W2[(size_t)(k0 + rrA) * L_ + q0 + segA * 16];
            *(uint4*)(wp)     = make_uint4(pk[0], pk[1], pk[2], pk[3]);
            *(uint4*)(wp + 8) = make_uint4(pk[4], pk[5], pk[6], pk[7]);
        }
        if (tid < 64)
            g_l1p[(size_t)strip * BL_ + (b << 11) + q0 + tid] =
                lsm[tid * 4] + lsm[tid * 4 + 1] + lsm[tid * 4 + 2] + lsm[tid * 4 + 3];
        __syncthreads();

        if (c + 2 < 8) cpS(c + 2, buf);
    }

    lsm[tid] = l2reg;
    __syncthreads();
    if (tid < 64)
        g_l2p[(size_t)part * BL_ + (b << 11) + k0 + tid] =
            lsm[tid] + lsm[tid + 64] + lsm[tid + 128] + lsm[tid + 192];
}

// ---------------- branch: pure fp16 GEMM, 128x256 full-D tile, 512 thr ----------------
__global__ void __launch_bounds__(512, 1) branch_kernel(float* __restrict__ out)
{
    extern __shared__ __align__(16) char smem[];
    const u32 sb = smem_u32(smem);
    const int tid = threadIdx.x, lane = tid & 31, w = tid >> 5;
    const int m0w = (w & 3) * 32, n0w = (w >> 2) * 64;
    const int row0 = blockIdx.x * 128;
    const int br = blockIdx.z & 1, b = blockIdx.z >> 1;

    const __half* wf = (br ? g_w2 : g_w1) + (size_t)(b * L_ + row0) * L_;
    const __half* vt = (br ? g_v2t : g_v1t) + (size_t)b * D_ * L_;
    float* ob = out + (br ? (size_t)B_ * L_ * D_ : 0) + (size_t)(b * L_ + row0) * D_;

    float* s_sc = (float*)(smem);
    if (tid < 128) {
        const int idx = (b << 11) + row0 + tid;
        float l = 0.f;
        if (br) {
            #pragma unroll
            for (int p = 0; p < 4; p++) l += g_l2p[(size_t)p * BL_ + idx];
        } else {
            #pragma unroll
            for (int s = 0; s < 32; s++) l += g_l1p[(size_t)s * BL_ + idx];
        }
        s_sc[tid] = 1.f / l;
    }
    __syncthreads();

    float acc[2][8][4];
    #pragma unroll
    for (int mi = 0; mi < 2; mi++)
        #pragma unroll
        for (int ni = 0; ni < 8; ni++)
            #pragma unroll
            for (int e = 0; e < 4; e++) acc[mi][ni][e] = 0.f;

    auto cpc = [&](int c, int stage) {
        const int i0 = c * 32;
        const u32 base = sb + TOFF + stage * BSTG;
        {
            int rr = tid >> 2, seg = tid & 3;
            CPA16(base + (u32)rr * 80 + seg * 16, wf + (size_t)rr * L_ + i0 + seg * 8);
        }
        #pragma unroll
        for (int t = 0; t < 2; t++) {
            int idx = tid + t * 512;
            int rr = idx >> 2, seg = idx & 3;
            CPA16(base + TB + (u32)rr * 80 + seg * 16, vt + (size_t)rr * L_ + i0 + seg * 8);
        }
    };

    cpc(0, 0); CPA_COMMIT();
    cpc(1, 1); CPA_COMMIT();
    cpc(2, 2); CPA_COMMIT();
    cpc(3, 3); CPA_COMMIT();

    for (int c = 0; c < 64; c++) {
        cpa_wait<3>();
        __syncthreads();
        gemm_chunk_f16(sb, c & 3, acc, lane, m0w, n0w);
        __syncthreads();
        if (c + 4 < 64) cpc(c + 4, (c + 4) & 3);
        CPA_COMMIT();
    }

    #pragma unroll
    for (int mi = 0; mi < 2; mi++) {
        const int rr = m0w + mi * 16 + (lane >> 2);
        const float sc0 = s_sc[rr], sc1 = s_sc[rr + 8];
        float* p0 = ob + (size_t)rr * D_ + n0w + 2 * (lane & 3);
        float* p1 = p0 + 8 * D_;
        #pragma unroll
        for (int ni = 0; ni < 8; ni++) {
            *(float2*)(p0 + ni * 8) = make_float2(acc[mi][ni][0] * sc0, acc[mi][ni][1] * sc0);
            *(float2*)(p1 + ni * 8) = make_float2(acc[mi][ni][2] * sc1, acc[mi][ni][3] * sc1);
        }
    }
}

// ---------------------------------------------------------------------------
extern "C" void kernel_launch(void* const* d_in, const int* in_sizes, int n_in,
                              void* d_out, int out_size)
{
    const float* queries = (const float*)d_in[0];
    const float* keys    = (const float*)d_in[1];
    const float* values1 = (const float*)d_in[2];
    const void*  mask1   = d_in[3];
    const float* values2 = (const float*)d_in[4];
    const void*  mask2   = d_in[5];
    const float* Wq      = (const float*)d_in[6];
    const float* Wk      = (const float*)d_in[7];
    const float* scaling = (const float*)d_in[8];
    float* out = (float*)d_out;

    cudaFuncSetAttribute(pre_kernel,     cudaFuncAttributeMaxDynamicSharedMemorySize, PSMEM);
    cudaFuncSetAttribute(scores_kernel,  cudaFuncAttributeMaxDynamicSharedMemorySize, SSMEM);
    cudaFuncSetAttribute(weights_kernel, cudaFuncAttributeMaxDynamicSharedMemorySize, WSMEM);
    cudaFuncSetAttribute(branch_kernel,  cudaFuncAttributeMaxDynamicSharedMemorySize, BSMEM);

    detect_mask_kernel<<<1, 256>>>((const unsigned char*)mask1);
    build_mask_kernel<<<(BL_ + 255) / 256, 256>>>(mask1, mask2);

    pre_kernel<<<2304, 256, PSMEM>>>(queries, keys, Wq, Wk, scaling, values1, values2);

    scores_kernel<<<dim3(L_ / 128, L_ / 128, B_), 256, SSMEM>>>();

    weights_kernel<<<dim3(32, 4, B_), 256, WSMEM>>>();

    branch_kernel<<<dim3(L_ / 128, 1, B_ * 2), 512, BSMEM>>>(out);
}